// round 3
// baseline (speedup 1.0000x reference)
#include <cuda_runtime.h>
#include <stdint.h>

#define NEG (-1e9f)
constexpr int B_   = 128;
constexpr int NPG  = 1024;
constexpr int N_   = B_ * NPG;
constexpr int D_   = 128;
constexpr int GD_  = 128;
constexpr int M_   = 24;
constexpr int MAXC = 512;
constexpr int G_   = 8;
constexpr int ND_  = 7;
constexpr int AT_  = 5;
constexpr int P_   = 28;

// Scratch (no allocation allowed in kernel_launch)
__device__ int   d_cube_node[B_ * MAXC];
__device__ int   d_group_node[B_ * G_];
__device__ float d_cm_gc[B_ * 128];   // per-batch global contribution + b1 (cube head)
__device__ float d_mn_gc[B_ * 128];   // per-batch global contribution + b1 (maneuver head)
__device__ int   d_mask_mode;         // 0 = uint8, 1 = int32, 2 = float32

__constant__ int c_IU[P_] = {0,0,0,0,0,0,0,1,1,1,1,1,1,2,2,2,2,2,3,3,3,3,4,4,4,5,5,6};
__constant__ int c_JU[P_] = {1,2,3,4,5,6,7,2,3,4,5,6,7,3,4,5,6,7,4,5,6,7,5,6,7,6,7,7};

// ---------------------------------------------------------------------------
// Mask dtype probe. action_type_mask is all-true by construction, so its first
// 4 bytes uniquely identify the storage dtype:
//   int32 ones   -> 0x00000001
//   float32 ones -> 0x3F800000
//   uint8 ones   -> 0x01010101
// ---------------------------------------------------------------------------
__global__ void probe_mask_kernel(const int* __restrict__ atm_raw) {
    int v = atm_raw[0];
    int mode = 0;
    if (v == 1) mode = 1;
    else if (v == 0x3F800000) mode = 2;
    d_mask_mode = mode;
}

__device__ __forceinline__ bool read_mask(const void* p, long i) {
    int mode = d_mask_mode;
    if (mode == 1) return ((const int*)p)[i] != 0;
    if (mode == 2) return ((const float*)p)[i] != 0.f;
    return ((const uint8_t*)p)[i] != 0;
}

// ---------------------------------------------------------------------------
// Index building: per-batch exclusive running position of masked nodes
// (matches reference _seg_pos for contiguous batch segments).
// ---------------------------------------------------------------------------
__global__ void init_idx_kernel() {
    int t = blockIdx.x * blockDim.x + threadIdx.x;
    if (t < B_ * MAXC) d_cube_node[t] = -1;
    if (t < B_ * G_)   d_group_node[t] = -1;
}

__global__ void build_idx_kernel(const void* __restrict__ cube_mask,
                                 const void* __restrict__ group_mask) {
    int warp = (blockIdx.x * blockDim.x + threadIdx.x) >> 5;
    int lane = threadIdx.x & 31;
    if (warp >= B_) return;
    int base = warp * NPG;
    int cc = 0, gc = 0;
    for (int c = 0; c < NPG; c += 32) {
        long node = base + c + lane;
        bool cm = read_mask(cube_mask, node);
        bool gm = read_mask(group_mask, node);
        unsigned cb = __ballot_sync(0xffffffffu, cm);
        unsigned gb = __ballot_sync(0xffffffffu, gm);
        unsigned lt = (1u << lane) - 1u;
        if (cm) { int p = cc + __popc(cb & lt); if (p < MAXC) d_cube_node[warp * MAXC + p] = (int)node; }
        if (gm) { int p = gc + __popc(gb & lt); if (p < G_)   d_group_node[warp * G_ + p] = (int)node; }
        cc += __popc(cb);
        gc += __popc(gb);
    }
}

// ---------------------------------------------------------------------------
// Per-batch global contribution: out[b][h] = b1[h] + sum_k global[b][k] * W1[128+k][h]
// which == 0 -> cube head, 1 -> maneuver head
// ---------------------------------------------------------------------------
__global__ __launch_bounds__(128) void gcontrib_kernel(const float* __restrict__ gf,
                                                       const float* __restrict__ W1,
                                                       const float* __restrict__ b1,
                                                       int which) {
    int b = blockIdx.x;
    int h = threadIdx.x;
    __shared__ float g[GD_];
    g[h] = gf[b * GD_ + h];
    __syncthreads();
    float s = b1[h];
    #pragma unroll 4
    for (int k = 0; k < GD_; k++) s = fmaf(g[k], W1[(128 + k) * 128 + h], s);
    float* outp = which ? d_mn_gc : d_cm_gc;
    outp[b * 128 + h] = s;
}

// ---------------------------------------------------------------------------
// ActionTypeHead: [B,GD] -> 64 -> 5
// ---------------------------------------------------------------------------
__global__ __launch_bounds__(64) void at_kernel(const float* __restrict__ gf,
                                                const void* __restrict__ atm,
                                                const float* __restrict__ W1,
                                                const float* __restrict__ b1,
                                                const float* __restrict__ W2,
                                                const float* __restrict__ b2,
                                                float* __restrict__ out) {
    int b = blockIdx.x, t = threadIdx.x;
    __shared__ float g[GD_];
    __shared__ float h[64];
    g[t] = gf[b * GD_ + t];
    g[t + 64] = gf[b * GD_ + t + 64];
    __syncthreads();
    float s = b1[t];
    #pragma unroll 4
    for (int k = 0; k < GD_; k++) s = fmaf(g[k], W1[k * 64 + t], s);
    h[t] = fmaxf(s, 0.f);
    __syncthreads();
    if (t < AT_) {
        float s2 = b2[t];
        #pragma unroll 4
        for (int k = 0; k < 64; k++) s2 = fmaf(h[k], W2[k * AT_ + t], s2);
        out[b * AT_ + t] = read_mask(atm, b * AT_ + t) ? s2 : NEG;
    }
}

// ---------------------------------------------------------------------------
// CubeMoveHead: dominant fused GEMM.
// 64 rows per block (one row = (batch, slot)); hidden 128; out 24.
// ---------------------------------------------------------------------------
__global__ __launch_bounds__(256) void cube_kernel(const float* __restrict__ nodef,
                                                   const float* __restrict__ W1,
                                                   const float* __restrict__ W2,
                                                   const float* __restrict__ b2,
                                                   const void* __restrict__ move_mask,
                                                   float* __restrict__ out) {
    __shared__ union SM {
        struct { float Xs[64][33]; float Ws[32][128]; } p1;
        struct { float Hs[64][130]; float W2s[128][24]; float b2s[24]; } p2;
    } sm;
    __shared__ int   nodes[64];
    __shared__ float gc[128];

    int t = threadIdx.x;
    int row0 = blockIdx.x * 64;       // 64 divides MAXC -> block stays in one batch
    int b = row0 / MAXC;

    if (t < 64)  nodes[t] = d_cube_node[row0 + t];
    if (t < 128) gc[t] = d_cm_gc[b * 128 + t];
    __syncthreads();

    float acc[4][8];
    #pragma unroll
    for (int i = 0; i < 4; i++)
        #pragma unroll
        for (int j = 0; j < 8; j++) acc[i][j] = 0.f;

    int tr = t >> 4;       // 0..15 -> rows 4*tr..4*tr+3
    int tc = t & 15;       // 0..15 -> cols 8*tc..8*tc+7

    for (int k0 = 0; k0 < D_; k0 += 32) {
        #pragma unroll
        for (int i = 0; i < 8; i++) {          // X tile: 64x32
            int lin = t + i * 256;
            int r = lin >> 5, c = lin & 31;
            int node = nodes[r];
            sm.p1.Xs[r][c] = (node >= 0) ? nodef[(size_t)node * D_ + k0 + c] : 0.f;
        }
        #pragma unroll
        for (int i = 0; i < 16; i++) {         // W tile: 32x128
            int lin = t + i * 256;
            int r = lin >> 7, c = lin & 127;
            sm.p1.Ws[r][c] = W1[(k0 + r) * 128 + c];
        }
        __syncthreads();
        #pragma unroll
        for (int kk = 0; kk < 32; kk++) {
            float a0 = sm.p1.Xs[4 * tr + 0][kk];
            float a1 = sm.p1.Xs[4 * tr + 1][kk];
            float a2 = sm.p1.Xs[4 * tr + 2][kk];
            float a3 = sm.p1.Xs[4 * tr + 3][kk];
            #pragma unroll
            for (int j = 0; j < 8; j++) {
                float bv = sm.p1.Ws[kk][8 * tc + j];
                acc[0][j] = fmaf(a0, bv, acc[0][j]);
                acc[1][j] = fmaf(a1, bv, acc[1][j]);
                acc[2][j] = fmaf(a2, bv, acc[2][j]);
                acc[3][j] = fmaf(a3, bv, acc[3][j]);
            }
        }
        __syncthreads();
    }

    // bias(+global contribution) + relu -> Hs
    #pragma unroll
    for (int i = 0; i < 4; i++)
        #pragma unroll
        for (int j = 0; j < 8; j++) {
            float v = acc[i][j] + gc[8 * tc + j];
            sm.p2.Hs[4 * tr + i][8 * tc + j] = fmaxf(v, 0.f);
        }
    #pragma unroll
    for (int i = 0; i < 12; i++) {             // W2: 128x24 = 3072
        int lin = t + i * 256;
        sm.p2.W2s[lin / 24][lin % 24] = W2[lin];
    }
    if (t < 24) sm.p2.b2s[t] = b2[t];
    __syncthreads();

    // Second GEMM 64x128 @ 128x24, fused masking + write
    for (int idx = t; idx < 64 * M_; idx += 256) {
        int r = idx / M_;
        int m = idx - r * M_;
        float s = sm.p2.b2s[m];
        #pragma unroll 8
        for (int k = 0; k < 128; k++) s = fmaf(sm.p2.Hs[r][k], sm.p2.W2s[k][m], s);
        int gslot = row0 + r;                       // == b*MAXC + slot
        size_t o = (size_t)gslot * M_ + m;          // index into [B, MAXC, M]
        bool ok = (nodes[r] >= 0) && read_mask(move_mask, (long)o);
        out[o] = ok ? s : NEG;
    }
}

// ---------------------------------------------------------------------------
// DockingHead: one block per batch. h1 = relu(u[i] + v[j] + w), then 128->64->1.
// ---------------------------------------------------------------------------
__global__ __launch_bounds__(128) void dock_kernel(const float* __restrict__ nodef,
                                                   const float* __restrict__ gf,
                                                   const void* __restrict__ dvm,
                                                   const float* __restrict__ W1,
                                                   const float* __restrict__ b1,
                                                   const float* __restrict__ W2,
                                                   const float* __restrict__ b2,
                                                   const float* __restrict__ W3,
                                                   const float* __restrict__ b3,
                                                   float* __restrict__ out) {
    __shared__ float gf8[G_][D_];
    __shared__ float gl[GD_];
    __shared__ float u[G_][128];
    __shared__ float v[G_][128];
    __shared__ float w[128];
    __shared__ float W2s[128 * 64];
    __shared__ float h1[128];
    __shared__ float red[4];

    int b = blockIdx.x, t = threadIdx.x;

    #pragma unroll
    for (int g = 0; g < G_; g++) {
        int n = d_group_node[b * G_ + g];
        gf8[g][t] = (n >= 0) ? nodef[(size_t)n * D_ + t] : 0.f;
    }
    gl[t] = gf[b * GD_ + t];
    for (int i = 0; i < 64; i++) W2s[t + i * 128] = W2[t + i * 128];
    __syncthreads();

    // u[g] = gf8[g] @ W1[0:128], v[g] = gf8[g] @ W1[128:256], w = gl @ W1[256:384] + b1
    float uacc[G_], vacc[G_];
    #pragma unroll
    for (int g = 0; g < G_; g++) { uacc[g] = 0.f; vacc[g] = 0.f; }
    float wacc = b1[t];
    for (int k = 0; k < D_; k++) {
        float wa = W1[k * 128 + t];
        float wb = W1[(128 + k) * 128 + t];
        float wc = W1[(256 + k) * 128 + t];
        #pragma unroll
        for (int g = 0; g < G_; g++) {
            uacc[g] = fmaf(gf8[g][k], wa, uacc[g]);
            vacc[g] = fmaf(gf8[g][k], wb, vacc[g]);
        }
        wacc = fmaf(gl[k], wc, wacc);
    }
    #pragma unroll
    for (int g = 0; g < G_; g++) { u[g][t] = uacc[g]; v[g][t] = vacc[g]; }
    w[t] = wacc;
    __syncthreads();

    float W3t = (t < 64) ? W3[t] : 0.f;
    for (int p = 0; p < P_; p++) {
        int i = c_IU[p], j = c_JU[p];
        h1[t] = fmaxf(u[i][t] + v[j][t] + w[t], 0.f);
        __syncthreads();
        float s2 = 0.f;
        if (t < 64) {
            s2 = b2[t];
            #pragma unroll 8
            for (int k = 0; k < 128; k++) s2 = fmaf(h1[k], W2s[k * 64 + t], s2);
            s2 = fmaxf(s2, 0.f) * W3t;
        }
        #pragma unroll
        for (int off = 16; off; off >>= 1) s2 += __shfl_down_sync(0xffffffffu, s2, off);
        if ((t & 31) == 0 && t < 64) red[t >> 5] = s2;
        __syncthreads();
        if (t == 0) {
            int ni = d_group_node[b * G_ + i];
            int nj = d_group_node[b * G_ + j];
            bool ok = read_mask(dvm, b * P_ + p) && (ni >= 0) && (nj >= 0);
            out[b * P_ + p] = ok ? (red[0] + red[1] + b3[0]) : NEG;
        }
        __syncthreads();
    }
}

// ---------------------------------------------------------------------------
// ManeuverHead: one block per batch. 256 -> 128 -> 7 per group.
// ---------------------------------------------------------------------------
__global__ __launch_bounds__(128) void man_kernel(const float* __restrict__ nodef,
                                                  const void* __restrict__ mvm,
                                                  const float* __restrict__ W1,
                                                  const float* __restrict__ W2,
                                                  const float* __restrict__ b2,
                                                  float* __restrict__ out) {
    __shared__ float gf8[G_][D_];
    __shared__ float H[G_][128];
    __shared__ float W2s[128 * ND_];
    int b = blockIdx.x, t = threadIdx.x;

    #pragma unroll
    for (int g = 0; g < G_; g++) {
        int n = d_group_node[b * G_ + g];
        gf8[g][t] = (n >= 0) ? nodef[(size_t)n * D_ + t] : 0.f;
    }
    #pragma unroll
    for (int i = 0; i < ND_; i++) W2s[t + i * 128] = W2[t + i * 128];
    __syncthreads();

    float gc = d_mn_gc[b * 128 + t];
    float acc[G_];
    #pragma unroll
    for (int g = 0; g < G_; g++) acc[g] = gc;
    for (int k = 0; k < D_; k++) {
        float wa = W1[k * 128 + t];
        #pragma unroll
        for (int g = 0; g < G_; g++) acc[g] = fmaf(gf8[g][k], wa, acc[g]);
    }
    #pragma unroll
    for (int g = 0; g < G_; g++) H[g][t] = fmaxf(acc[g], 0.f);
    __syncthreads();

    if (t < G_ * ND_) {
        int g = t / ND_, d = t - g * ND_;
        float s = b2[d];
        #pragma unroll 8
        for (int k = 0; k < 128; k++) s = fmaf(H[g][k], W2s[k * ND_ + d], s);
        int n = d_group_node[b * G_ + g];
        bool ok = (n >= 0) && read_mask(mvm, b * G_ * ND_ + t);
        out[b * G_ * ND_ + t] = ok ? s : NEG;
    }
}

// ---------------------------------------------------------------------------
extern "C" void kernel_launch(void* const* d_in, const int* in_sizes, int n_in,
                              void* d_out, int out_size) {
    const float* nodef      = (const float*)d_in[0];
    const float* gf         = (const float*)d_in[1];
    const void*  atm        = d_in[2];
    const void*  cube_mask  = d_in[3];
    const void*  group_mask = d_in[4];
    /* d_in[5] = batch (unused; segments are contiguous) */
    const void*  move_mask  = d_in[6];
    const void*  dvm        = d_in[7];
    const void*  mvm        = d_in[8];
    const float* at_W1 = (const float*)d_in[9];
    const float* at_b1 = (const float*)d_in[10];
    const float* at_W2 = (const float*)d_in[11];
    const float* at_b2 = (const float*)d_in[12];
    const float* cm_W1 = (const float*)d_in[13];
    const float* cm_b1 = (const float*)d_in[14];
    const float* cm_W2 = (const float*)d_in[15];
    const float* cm_b2 = (const float*)d_in[16];
    const float* dk_W1 = (const float*)d_in[17];
    const float* dk_b1 = (const float*)d_in[18];
    const float* dk_W2 = (const float*)d_in[19];
    const float* dk_b2 = (const float*)d_in[20];
    const float* dk_W3 = (const float*)d_in[21];
    const float* dk_b3 = (const float*)d_in[22];
    const float* mn_W1 = (const float*)d_in[23];
    const float* mn_b1 = (const float*)d_in[24];
    const float* mn_W2 = (const float*)d_in[25];
    const float* mn_b2 = (const float*)d_in[26];

    float* out      = (float*)d_out;
    float* out_at   = out;
    float* out_cube = out + (size_t)B_ * AT_;
    float* out_dock = out_cube + (size_t)B_ * MAXC * M_;
    float* out_man  = out_dock + (size_t)B_ * P_;

    probe_mask_kernel<<<1, 1>>>((const int*)atm);
    init_idx_kernel<<<(B_ * MAXC + 255) / 256, 256>>>();
    build_idx_kernel<<<(B_ * 32 + 255) / 256, 256>>>(cube_mask, group_mask);

    gcontrib_kernel<<<B_, 128>>>(gf, cm_W1, cm_b1, 0);
    gcontrib_kernel<<<B_, 128>>>(gf, mn_W1, mn_b1, 1);

    at_kernel<<<B_, 64>>>(gf, atm, at_W1, at_b1, at_W2, at_b2, out_at);
    cube_kernel<<<(B_ * MAXC) / 64, 256>>>(nodef, cm_W1, cm_W2, cm_b2, move_mask, out_cube);
    dock_kernel<<<B_, 128>>>(nodef, gf, dvm, dk_W1, dk_b1, dk_W2, dk_b2, dk_W3, dk_b3, out_dock);
    man_kernel<<<B_, 128>>>(nodef, mvm, mn_W1, mn_W2, mn_b2, out_man);
}

// round 4
// speedup vs baseline: 1.6141x; 1.6141x over previous
#include <cuda_runtime.h>
#include <stdint.h>

#define NEG (-1e9f)
constexpr int B_   = 128;
constexpr int NPG  = 1024;
constexpr int M_   = 24;
constexpr int MAXC = 512;
constexpr int G_   = 8;
constexpr int ND_  = 7;
constexpr int AT_  = 5;
constexpr int P_   = 28;

__device__ int   d_cube_node[B_ * MAXC];
__device__ int   d_group_node[B_ * G_];
__device__ float d_cm_gc[B_ * 128];
__device__ float d_mn_gc[B_ * 128];

__constant__ int c_IU[P_] = {0,0,0,0,0,0,0,1,1,1,1,1,1,2,2,2,2,2,3,3,3,3,4,4,4,5,5,6};
__constant__ int c_JU[P_] = {1,2,3,4,5,6,7,2,3,4,5,6,7,3,4,5,6,7,4,5,6,7,5,6,7,6,7,7};

// masks arrive as int32 ones (probe: atm[0]==1). Keep dtype-general fallback.
__device__ __forceinline__ int mask_mode(const int* __restrict__ atm) {
    int v = __ldg(atm);
    if (v == 1) return 1;
    if (v == 0x3F800000) return 2;
    return 0;
}
__device__ __forceinline__ bool read_mask(const void* p, long i, int mode) {
    if (mode == 1) return ((const int*)p)[i] != 0;
    if (mode == 2) return ((const float*)p)[i] != 0.f;
    return ((const uint8_t*)p)[i] != 0;
}

// -------- f32x2 packed helpers (sm_103a) --------
__device__ __forceinline__ uint64_t pack2(float x, float y) {
    uint64_t r; asm("mov.b64 %0, {%1, %2};" : "=l"(r) : "f"(x), "f"(y)); return r;
}
__device__ __forceinline__ void fma2(uint64_t& d, uint64_t a, uint64_t b) {
    asm("fma.rn.f32x2 %0, %1, %2, %0;" : "+l"(d) : "l"(a), "l"(b));
}
__device__ __forceinline__ float2 unpk(uint64_t v) {
    float2 f; asm("mov.b64 {%0, %1}, %2;" : "=f"(f.x), "=f"(f.y) : "l"(v)); return f;
}

// ---------------------------------------------------------------------------
// setup: per-batch global contributions (cube + maneuver heads) and index build
// ---------------------------------------------------------------------------
__global__ __launch_bounds__(128) void setup_kernel(
    const float* __restrict__ gf,
    const float* __restrict__ cmW1, const float* __restrict__ cmb1,
    const float* __restrict__ mnW1, const float* __restrict__ mnb1,
    const void* __restrict__ cube_mask, const void* __restrict__ group_mask,
    const int* __restrict__ atm)
{
    const int b = blockIdx.x, t = threadIdx.x;
    const int mode = mask_mode(atm);
    __shared__ float g[128];
    g[t] = gf[b * 128 + t];
    __syncthreads();

    // gcontrib for both heads, 4 load streams each -> high MLP
    {
        const float* Wc = cmW1 + 128 * 128 + t;
        const float* Wm = mnW1 + 128 * 128 + t;
        float c0 = 0.f, c1 = 0.f, m0 = 0.f, m1 = 0.f;
        #pragma unroll
        for (int k = 0; k < 128; k += 2) {
            c0 = fmaf(g[k],     __ldg(Wc + k * 128),       c0);
            c1 = fmaf(g[k + 1], __ldg(Wc + (k + 1) * 128), c1);
            m0 = fmaf(g[k],     __ldg(Wm + k * 128),       m0);
            m1 = fmaf(g[k + 1], __ldg(Wm + (k + 1) * 128), m1);
        }
        d_cm_gc[b * 128 + t] = __ldg(cmb1 + t) + (c0 + c1);
        d_mn_gc[b * 128 + t] = __ldg(mnb1 + t) + (m0 + m1);
    }

    // warp 0: index build (seg_pos semantics over contiguous batch segment)
    if (t < 32) {
        const int lane = t;
        const unsigned full = 0xffffffffu;
        int cc = 0, gc = 0;
        if (mode == 1) {
            const int4* cm4 = (const int4*)cube_mask + b * 256;
            const int4* gm4 = (const int4*)group_mask + b * 256;
            for (int c = 0; c < 1024; c += 128) {
                int4 cv = __ldg(cm4 + (c >> 2) + lane);
                int4 gv = __ldg(gm4 + (c >> 2) + lane);
                unsigned cb = (cv.x != 0) | ((cv.y != 0) << 1) | ((cv.z != 0) << 2) | ((cv.w != 0) << 3);
                unsigned gb = (gv.x != 0) | ((gv.y != 0) << 1) | ((gv.z != 0) << 2) | ((gv.w != 0) << 3);
                // warp inclusive scan of per-lane popcounts
                int cs = __popc(cb), gs = __popc(gb);
                int csi = cs, gsi = gs;
                #pragma unroll
                for (int off = 1; off < 32; off <<= 1) {
                    int v1 = __shfl_up_sync(full, csi, off);
                    int v2 = __shfl_up_sync(full, gsi, off);
                    if (lane >= off) { csi += v1; gsi += v2; }
                }
                int cex = csi - cs, gex = gsi - gs;
                int base = b * NPG + c + lane * 4;
                #pragma unroll
                for (int j = 0; j < 4; j++) {
                    if ((cb >> j) & 1) {
                        int p = cc + cex + __popc(cb & ((1u << j) - 1u));
                        if (p < MAXC) d_cube_node[b * MAXC + p] = base + j;
                    }
                    if ((gb >> j) & 1) {
                        int p = gc + gex + __popc(gb & ((1u << j) - 1u));
                        if (p < G_) d_group_node[b * G_ + p] = base + j;
                    }
                }
                cc += __shfl_sync(full, csi, 31);
                gc += __shfl_sync(full, gsi, 31);
            }
        } else {
            for (int c = 0; c < NPG; c += 32) {
                long node = (long)b * NPG + c + lane;
                bool cm = read_mask(cube_mask, node, mode);
                bool gm = read_mask(group_mask, node, mode);
                unsigned cb = __ballot_sync(full, cm);
                unsigned gb = __ballot_sync(full, gm);
                unsigned lt = (1u << lane) - 1u;
                if (cm) { int p = cc + __popc(cb & lt); if (p < MAXC) d_cube_node[b * MAXC + p] = (int)node; }
                if (gm) { int p = gc + __popc(gb & lt); if (p < G_)   d_group_node[b * G_ + p] = (int)node; }
                cc += __popc(cb);
                gc += __popc(gb);
            }
        }
        for (int p = cc + lane; p < MAXC; p += 32) d_cube_node[b * MAXC + p] = -1;
        for (int p = gc + lane; p < G_; p += 32)   d_group_node[b * G_ + p] = -1;
    }
}

// ---------------------------------------------------------------------------
// CubeMoveHead: 64 rows x 128 hidden per block, 128 threads, f32x2 FMA.
// Thread tile 8 rows x 8 cols (cols 4tx..4tx+3 and 64+4tx..64+4tx+3).
// ---------------------------------------------------------------------------
__global__ __launch_bounds__(128) void cube_kernel(
    const float* __restrict__ nodef, const float* __restrict__ W1,
    const float* __restrict__ W2, const float* __restrict__ b2,
    const void* __restrict__ move_mask, const int* __restrict__ atm,
    float* __restrict__ out)
{
    __shared__ union SM {
        struct { float XsT[16][68]; float Ws[16][132]; } a;
        float Hs[64][132];
    } sm;
    __shared__ float W2s[128 * 24];
    __shared__ float b2s[24];
    __shared__ int   nodes[64];
    __shared__ float gcs[128];

    const int t = threadIdx.x;
    const int row0 = blockIdx.x * 64;     // 64 | MAXC -> single batch per block
    const int b = row0 >> 9;
    const int tx = t & 15, ty = t >> 4;
    const int mode = mask_mode(atm);

    if (t < 64) nodes[t] = d_cube_node[row0 + t];
    gcs[t] = d_cm_gc[b * 128 + t];
    #pragma unroll
    for (int i = 0; i < 24; i++) W2s[t + i * 128] = __ldg(W2 + t + i * 128);
    if (t < 24) b2s[t] = __ldg(b2 + t);
    __syncthreads();

    uint64_t acc[8][4];
    #pragma unroll
    for (int i = 0; i < 8; i++)
        #pragma unroll
        for (int j = 0; j < 4; j++) acc[i][j] = 0ull;

    for (int ch = 0; ch < 8; ch++) {
        const int k0 = ch * 16;
        #pragma unroll
        for (int i = 0; i < 8; i++) {            // X^T tile 16k x 64r
            int lin = t + i * 128, r = lin >> 4, c = lin & 15;
            int nd = nodes[r];
            sm.a.XsT[c][r] = (nd >= 0) ? __ldg(nodef + (size_t)nd * 128 + k0 + c) : 0.f;
        }
        #pragma unroll
        for (int i = 0; i < 16; i++) {           // W tile 16k x 128c
            int lin = t + i * 128, r = lin >> 7, c = lin & 127;
            sm.a.Ws[r][c] = __ldg(W1 + (size_t)(k0 + r) * 128 + c);
        }
        __syncthreads();
        #pragma unroll
        for (int kk = 0; kk < 16; kk++) {
            float4 a0 = *(const float4*)&sm.a.XsT[kk][8 * ty];
            float4 a1 = *(const float4*)&sm.a.XsT[kk][8 * ty + 4];
            uint64_t B0 = *(const uint64_t*)&sm.a.Ws[kk][4 * tx];
            uint64_t B1 = *(const uint64_t*)&sm.a.Ws[kk][4 * tx + 2];
            uint64_t B2 = *(const uint64_t*)&sm.a.Ws[kk][64 + 4 * tx];
            uint64_t B3 = *(const uint64_t*)&sm.a.Ws[kk][64 + 4 * tx + 2];
            float av[8] = {a0.x, a0.y, a0.z, a0.w, a1.x, a1.y, a1.z, a1.w};
            #pragma unroll
            for (int i = 0; i < 8; i++) {
                uint64_t A = pack2(av[i], av[i]);
                fma2(acc[i][0], A, B0);
                fma2(acc[i][1], A, B1);
                fma2(acc[i][2], A, B2);
                fma2(acc[i][3], A, B3);
            }
        }
        __syncthreads();
    }

    // epilogue GEMM1: + global contribution, relu -> Hs
    #pragma unroll
    for (int i = 0; i < 8; i++) {
        int r = 8 * ty + i;
        float2 f;
        f = unpk(acc[i][0]);
        sm.Hs[r][4 * tx + 0]      = fmaxf(f.x + gcs[4 * tx + 0], 0.f);
        sm.Hs[r][4 * tx + 1]      = fmaxf(f.y + gcs[4 * tx + 1], 0.f);
        f = unpk(acc[i][1]);
        sm.Hs[r][4 * tx + 2]      = fmaxf(f.x + gcs[4 * tx + 2], 0.f);
        sm.Hs[r][4 * tx + 3]      = fmaxf(f.y + gcs[4 * tx + 3], 0.f);
        f = unpk(acc[i][2]);
        sm.Hs[r][64 + 4 * tx + 0] = fmaxf(f.x + gcs[64 + 4 * tx + 0], 0.f);
        sm.Hs[r][64 + 4 * tx + 1] = fmaxf(f.y + gcs[64 + 4 * tx + 1], 0.f);
        f = unpk(acc[i][3]);
        sm.Hs[r][64 + 4 * tx + 2] = fmaxf(f.x + gcs[64 + 4 * tx + 2], 0.f);
        sm.Hs[r][64 + 4 * tx + 3] = fmaxf(f.y + gcs[64 + 4 * tx + 3], 0.f);
    }
    __syncthreads();

    // GEMM2: 64x128 @ 128x24, packed along output cols. 2 rows x 3 col-pairs.
    const int rg = t >> 2;
    const int m0 = 6 * (t & 3);
    uint64_t c2[2][3];
    #pragma unroll
    for (int i = 0; i < 2; i++)
        #pragma unroll
        for (int j = 0; j < 3; j++) c2[i][j] = 0ull;

    #pragma unroll 4
    for (int k = 0; k < 128; k++) {
        uint64_t w0 = *(const uint64_t*)&W2s[k * 24 + m0];
        uint64_t w1 = *(const uint64_t*)&W2s[k * 24 + m0 + 2];
        uint64_t w2 = *(const uint64_t*)&W2s[k * 24 + m0 + 4];
        float h0 = sm.Hs[2 * rg][k];
        float h1 = sm.Hs[2 * rg + 1][k];
        uint64_t H0 = pack2(h0, h0), H1 = pack2(h1, h1);
        fma2(c2[0][0], H0, w0); fma2(c2[0][1], H0, w1); fma2(c2[0][2], H0, w2);
        fma2(c2[1][0], H1, w0); fma2(c2[1][1], H1, w1); fma2(c2[1][2], H1, w2);
    }

    #pragma unroll
    for (int rr = 0; rr < 2; rr++) {
        int r = 2 * rg + rr;
        bool valid = nodes[r] >= 0;
        long gbase = (long)(row0 + r) * 24 + m0;
        #pragma unroll
        for (int j = 0; j < 3; j++) {
            float2 f = unpk(c2[rr][j]);
            long o = gbase + 2 * j;
            out[o]     = (valid && read_mask(move_mask, o, mode))     ? f.x + b2s[m0 + 2 * j]     : NEG;
            out[o + 1] = (valid && read_mask(move_mask, o + 1, mode)) ? f.y + b2s[m0 + 2 * j + 1] : NEG;
        }
    }
}

// ---------------------------------------------------------------------------
// Fused heads: ActionType + Docking + Maneuver. One block per batch, 128 thr.
// ---------------------------------------------------------------------------
__global__ __launch_bounds__(128) void heads_kernel(
    const float* __restrict__ nodef, const float* __restrict__ gf,
    const int* __restrict__ atm, const void* __restrict__ dvm, const void* __restrict__ mvm,
    const float* __restrict__ at_W1, const float* __restrict__ at_b1,
    const float* __restrict__ at_W2, const float* __restrict__ at_b2,
    const float* __restrict__ dk_W1, const float* __restrict__ dk_b1,
    const float* __restrict__ dk_W2, const float* __restrict__ dk_b2,
    const float* __restrict__ dk_W3, const float* __restrict__ dk_b3,
    const float* __restrict__ mn_W1, const float* __restrict__ mn_W2,
    const float* __restrict__ mn_b2,
    float* __restrict__ out_at, float* __restrict__ out_dock, float* __restrict__ out_man)
{
    __shared__ float gf8[G_][128];
    __shared__ float gl[128];
    __shared__ float uu[G_][128], vv[G_][128], ww[128];
    __shared__ float manH[G_][128];
    __shared__ float ath[64];
    __shared__ float h1[2][128];
    __shared__ float red[4];
    __shared__ int   gid[G_];

    const int b = blockIdx.x, t = threadIdx.x;
    const int mode = mask_mode(atm);

    if (t < G_) gid[t] = d_group_node[b * G_ + t];
    gl[t] = gf[b * 128 + t];
    __syncthreads();
    #pragma unroll
    for (int i = 0; i < 8; i++) {
        int idx = t + i * 128;
        int g = idx >> 7, c = idx & 127;
        int n = gid[g];
        gf8[g][c] = (n >= 0) ? __ldg(nodef + (size_t)n * 128 + c) : 0.f;
    }
    __syncthreads();

    // ---- fused hidden-layer pass ----
    {
        float ua[G_], va[G_], ma[G_];
        #pragma unroll
        for (int g = 0; g < G_; g++) { ua[g] = 0.f; va[g] = 0.f; }
        float gcm = d_mn_gc[b * 128 + t];
        #pragma unroll
        for (int g = 0; g < G_; g++) ma[g] = gcm;
        float wv = __ldg(dk_b1 + t);
        float av = (t < 64) ? __ldg(at_b1 + t) : 0.f;
        #pragma unroll 2
        for (int k = 0; k < 128; k++) {
            float wa = __ldg(dk_W1 + k * 128 + t);
            float wb = __ldg(dk_W1 + (128 + k) * 128 + t);
            float wc = __ldg(dk_W1 + (256 + k) * 128 + t);
            float wm = __ldg(mn_W1 + k * 128 + t);
            float gk = gl[k];
            #pragma unroll
            for (int g = 0; g < G_; g++) {
                float x = gf8[g][k];
                ua[g] = fmaf(x, wa, ua[g]);
                va[g] = fmaf(x, wb, va[g]);
                ma[g] = fmaf(x, wm, ma[g]);
            }
            wv = fmaf(gk, wc, wv);
            if (t < 64) av = fmaf(gk, __ldg(at_W1 + k * 64 + t), av);
        }
        #pragma unroll
        for (int g = 0; g < G_; g++) {
            uu[g][t] = ua[g];
            vv[g][t] = va[g];
            manH[g][t] = fmaxf(ma[g], 0.f);
        }
        ww[t] = wv;
        if (t < 64) ath[t] = fmaxf(av, 0.f);
    }
    __syncthreads();

    // ---- maneuver + action-type outputs ----
    if (t < G_ * ND_) {
        int g = t / ND_, d = t - g * ND_;
        float s = __ldg(mn_b2 + d);
        #pragma unroll 8
        for (int k = 0; k < 128; k++) s = fmaf(manH[g][k], __ldg(mn_W2 + k * ND_ + d), s);
        bool ok = (gid[g] >= 0) && read_mask(mvm, b * G_ * ND_ + t, mode);
        out_man[b * G_ * ND_ + t] = ok ? s : NEG;
    } else if (t >= 64 && t < 64 + AT_) {
        int a = t - 64;
        float s = __ldg(at_b2 + a);
        #pragma unroll 8
        for (int k = 0; k < 64; k++) s = fmaf(ath[k], __ldg(at_W2 + k * AT_ + a), s);
        out_at[b * AT_ + a] = read_mask(atm, b * AT_ + a, mode) ? s : NEG;
    }
    __syncthreads();

    // ---- docking: 2 pairs per pass ----
    const int which = t >> 6, tt = t & 63;
    const float W3t = __ldg(dk_W3 + tt);
    const float b2t = __ldg(dk_b2 + tt);
    const float b3v = __ldg(dk_b3);
    for (int pp = 0; pp < P_; pp += 2) {
        int i0 = c_IU[pp], j0 = c_JU[pp];
        int i1 = c_IU[pp + 1], j1 = c_JU[pp + 1];
        h1[0][t] = fmaxf(uu[i0][t] + vv[j0][t] + ww[t], 0.f);
        h1[1][t] = fmaxf(uu[i1][t] + vv[j1][t] + ww[t], 0.f);
        __syncthreads();
        const float* hp = h1[which];
        float s2 = b2t;
        #pragma unroll 8
        for (int k = 0; k < 128; k++) s2 = fmaf(hp[k], __ldg(dk_W2 + k * 64 + tt), s2);
        s2 = fmaxf(s2, 0.f) * W3t;
        #pragma unroll
        for (int off = 16; off; off >>= 1) s2 += __shfl_down_sync(0xffffffffu, s2, off);
        if ((t & 31) == 0) red[t >> 5] = s2;
        __syncthreads();
        if (t < 2) {
            int p = pp + t;
            int ii = t ? i1 : i0, jj = t ? j1 : j0;
            bool ok = read_mask(dvm, b * P_ + p, mode) && gid[ii] >= 0 && gid[jj] >= 0;
            out_dock[b * P_ + p] = ok ? (red[2 * t] + red[2 * t + 1] + b3v) : NEG;
        }
        __syncthreads();
    }
}

// ---------------------------------------------------------------------------
extern "C" void kernel_launch(void* const* d_in, const int* in_sizes, int n_in,
                              void* d_out, int out_size) {
    const float* nodef      = (const float*)d_in[0];
    const float* gf         = (const float*)d_in[1];
    const int*   atm        = (const int*)d_in[2];
    const void*  cube_mask  = d_in[3];
    const void*  group_mask = d_in[4];
    /* d_in[5] = batch (unused; segments contiguous) */
    const void*  move_mask  = d_in[6];
    const void*  dvm        = d_in[7];
    const void*  mvm        = d_in[8];
    const float* at_W1 = (const float*)d_in[9];
    const float* at_b1 = (const float*)d_in[10];
    const float* at_W2 = (const float*)d_in[11];
    const float* at_b2 = (const float*)d_in[12];
    const float* cm_W1 = (const float*)d_in[13];
    const float* cm_b1 = (const float*)d_in[14];
    const float* cm_W2 = (const float*)d_in[15];
    const float* cm_b2 = (const float*)d_in[16];
    const float* dk_W1 = (const float*)d_in[17];
    const float* dk_b1 = (const float*)d_in[18];
    const float* dk_W2 = (const float*)d_in[19];
    const float* dk_b2 = (const float*)d_in[20];
    const float* dk_W3 = (const float*)d_in[21];
    const float* dk_b3 = (const float*)d_in[22];
    const float* mn_W1 = (const float*)d_in[23];
    const float* mn_b1 = (const float*)d_in[24];
    const float* mn_W2 = (const float*)d_in[25];
    const float* mn_b2 = (const float*)d_in[26];

    float* out      = (float*)d_out;
    float* out_at   = out;
    float* out_cube = out + (size_t)B_ * AT_;
    float* out_dock = out_cube + (size_t)B_ * MAXC * M_;
    float* out_man  = out_dock + (size_t)B_ * P_;

    setup_kernel<<<B_, 128>>>(gf, cm_W1, cm_b1, mn_W1, mn_b1, cube_mask, group_mask, atm);
    cube_kernel<<<(B_ * MAXC) / 64, 128>>>(nodef, cm_W1, cm_W2, cm_b2, move_mask, atm, out_cube);
    heads_kernel<<<B_, 128>>>(nodef, gf, atm, dvm, mvm,
                              at_W1, at_b1, at_W2, at_b2,
                              dk_W1, dk_b1, dk_W2, dk_b2, dk_W3, dk_b3,
                              mn_W1, mn_W2, mn_b2,
                              out_at, out_dock, out_man);
}

// round 5
// speedup vs baseline: 2.0975x; 1.2995x over previous
#include <cuda_runtime.h>
#include <stdint.h>

#define NEG (-1e9f)
constexpr int B_   = 128;
constexpr int NPG  = 1024;
constexpr int M_   = 24;
constexpr int MAXC = 512;
constexpr int G_   = 8;
constexpr int ND_  = 7;
constexpr int AT_  = 5;
constexpr int P_   = 28;

__device__ int   d_cube_node[B_ * MAXC];
__device__ int   d_group_node[B_ * G_];
__device__ float d_cm_gc[B_ * 128];

__constant__ int c_IU[P_] = {0,0,0,0,0,0,0,1,1,1,1,1,1,2,2,2,2,2,3,3,3,3,4,4,4,5,5,6};
__constant__ int c_JU[P_] = {1,2,3,4,5,6,7,2,3,4,5,6,7,3,4,5,6,7,4,5,6,7,5,6,7,6,7,7};

// masks arrive as int32 ones (probe: atm[0]==1). Keep dtype-general fallback.
__device__ __forceinline__ int mask_mode(const int* __restrict__ atm) {
    int v = __ldg(atm);
    if (v == 1) return 1;
    if (v == 0x3F800000) return 2;
    return 0;
}
__device__ __forceinline__ bool read_mask(const void* p, long i, int mode) {
    if (mode == 1) return ((const int*)p)[i] != 0;
    if (mode == 2) return ((const float*)p)[i] != 0.f;
    return ((const uint8_t*)p)[i] != 0;
}

// -------- f32x2 packed helpers (sm_103a) --------
__device__ __forceinline__ uint64_t pack2(float x, float y) {
    uint64_t r; asm("mov.b64 %0, {%1, %2};" : "=l"(r) : "f"(x), "f"(y)); return r;
}
__device__ __forceinline__ void fma2(uint64_t& d, uint64_t a, uint64_t b) {
    asm("fma.rn.f32x2 %0, %1, %2, %0;" : "+l"(d) : "l"(a), "l"(b));
}
__device__ __forceinline__ float2 unpk(uint64_t v) {
    float2 f; asm("mov.b64 {%0, %1}, %2;" : "=f"(f.x), "=f"(f.y) : "l"(v)); return f;
}

// ---------------------------------------------------------------------------
// setup: cube-head global contribution (float4 k-split) + index build (warp 4)
// ---------------------------------------------------------------------------
__global__ __launch_bounds__(160) void setup_kernel(
    const float* __restrict__ gf,
    const float* __restrict__ cmW1, const float* __restrict__ cmb1,
    const void* __restrict__ cube_mask, const void* __restrict__ group_mask,
    const int* __restrict__ atm)
{
    const int b = blockIdx.x, t = threadIdx.x;
    __shared__ float g[128];
    __shared__ float sred[4][128];

    if (t < 128) g[t] = gf[b * 128 + t];
    __syncthreads();

    if (t < 128) {
        // warps 0-3: k-split gcontrib, float4 weight loads -> high MLP
        const int w = t >> 5, l = t & 31;
        const float4* W4 = (const float4*)cmW1;
        float4 a = make_float4(0.f, 0.f, 0.f, 0.f);
        #pragma unroll
        for (int kk = 0; kk < 32; kk++) {
            int k = 32 * w + kk;
            float4 wv = __ldg(&W4[(128 + k) * 32 + l]);
            float gk = g[k];
            a.x = fmaf(gk, wv.x, a.x);
            a.y = fmaf(gk, wv.y, a.y);
            a.z = fmaf(gk, wv.z, a.z);
            a.w = fmaf(gk, wv.w, a.w);
        }
        *(float4*)&sred[w][4 * l] = a;
    } else {
        // warp 4: index build (seg_pos over contiguous batch segment)
        const int lane = t - 128;
        const unsigned full = 0xffffffffu;
        const int mode = mask_mode(atm);
        int cc = 0, gc = 0;
        if (mode == 1) {
            const int4* cm4 = (const int4*)cube_mask + b * 256;
            const int4* gm4 = (const int4*)group_mask + b * 256;
            for (int c = 0; c < 1024; c += 128) {
                int4 cv = __ldg(cm4 + (c >> 2) + lane);
                int4 gv = __ldg(gm4 + (c >> 2) + lane);
                unsigned cb = (cv.x != 0) | ((cv.y != 0) << 1) | ((cv.z != 0) << 2) | ((cv.w != 0) << 3);
                unsigned gb = (gv.x != 0) | ((gv.y != 0) << 1) | ((gv.z != 0) << 2) | ((gv.w != 0) << 3);
                int cs = __popc(cb), gs = __popc(gb);
                int csi = cs, gsi = gs;
                #pragma unroll
                for (int off = 1; off < 32; off <<= 1) {
                    int v1 = __shfl_up_sync(full, csi, off);
                    int v2 = __shfl_up_sync(full, gsi, off);
                    if (lane >= off) { csi += v1; gsi += v2; }
                }
                int cex = csi - cs, gex = gsi - gs;
                int base = b * NPG + c + lane * 4;
                #pragma unroll
                for (int j = 0; j < 4; j++) {
                    if ((cb >> j) & 1) {
                        int p = cc + cex + __popc(cb & ((1u << j) - 1u));
                        if (p < MAXC) d_cube_node[b * MAXC + p] = base + j;
                    }
                    if ((gb >> j) & 1) {
                        int p = gc + gex + __popc(gb & ((1u << j) - 1u));
                        if (p < G_) d_group_node[b * G_ + p] = base + j;
                    }
                }
                cc += __shfl_sync(full, csi, 31);
                gc += __shfl_sync(full, gsi, 31);
            }
        } else {
            for (int c = 0; c < NPG; c += 32) {
                long node = (long)b * NPG + c + lane;
                bool cm = read_mask(cube_mask, node, mode);
                bool gm = read_mask(group_mask, node, mode);
                unsigned cb = __ballot_sync(full, cm);
                unsigned gb = __ballot_sync(full, gm);
                unsigned lt = (1u << lane) - 1u;
                if (cm) { int p = cc + __popc(cb & lt); if (p < MAXC) d_cube_node[b * MAXC + p] = (int)node; }
                if (gm) { int p = gc + __popc(gb & lt); if (p < G_)   d_group_node[b * G_ + p] = (int)node; }
                cc += __popc(cb);
                gc += __popc(gb);
            }
        }
        for (int p = cc + lane; p < MAXC; p += 32) d_cube_node[b * MAXC + p] = -1;
        for (int p = gc + lane; p < G_; p += 32)   d_group_node[b * G_ + p] = -1;
    }
    __syncthreads();
    if (t < 128)
        d_cm_gc[b * 128 + t] = __ldg(cmb1 + t) +
            ((sred[0][t] + sred[1][t]) + (sred[2][t] + sred[3][t]));
}

// ---------------------------------------------------------------------------
// CubeMoveHead: 64 rows x 128 hidden per block, 128 threads, f32x2 FMA.
// (unchanged from R4 — near its fma2 floor)
// ---------------------------------------------------------------------------
__global__ __launch_bounds__(128) void cube_kernel(
    const float* __restrict__ nodef, const float* __restrict__ W1,
    const float* __restrict__ W2, const float* __restrict__ b2,
    const void* __restrict__ move_mask, const int* __restrict__ atm,
    float* __restrict__ out)
{
    __shared__ union SM {
        struct { float XsT[16][68]; float Ws[16][132]; } a;
        float Hs[64][132];
    } sm;
    __shared__ float W2s[128 * 24];
    __shared__ float b2s[24];
    __shared__ int   nodes[64];
    __shared__ float gcs[128];

    const int t = threadIdx.x;
    const int row0 = blockIdx.x * 64;
    const int b = row0 >> 9;
    const int tx = t & 15, ty = t >> 4;
    const int mode = mask_mode(atm);

    if (t < 64) nodes[t] = d_cube_node[row0 + t];
    gcs[t] = d_cm_gc[b * 128 + t];
    #pragma unroll
    for (int i = 0; i < 24; i++) W2s[t + i * 128] = __ldg(W2 + t + i * 128);
    if (t < 24) b2s[t] = __ldg(b2 + t);
    __syncthreads();

    uint64_t acc[8][4];
    #pragma unroll
    for (int i = 0; i < 8; i++)
        #pragma unroll
        for (int j = 0; j < 4; j++) acc[i][j] = 0ull;

    for (int ch = 0; ch < 8; ch++) {
        const int k0 = ch * 16;
        #pragma unroll
        for (int i = 0; i < 8; i++) {
            int lin = t + i * 128, r = lin >> 4, c = lin & 15;
            int nd = nodes[r];
            sm.a.XsT[c][r] = (nd >= 0) ? __ldg(nodef + (size_t)nd * 128 + k0 + c) : 0.f;
        }
        #pragma unroll
        for (int i = 0; i < 16; i++) {
            int lin = t + i * 128, r = lin >> 7, c = lin & 127;
            sm.a.Ws[r][c] = __ldg(W1 + (size_t)(k0 + r) * 128 + c);
        }
        __syncthreads();
        #pragma unroll
        for (int kk = 0; kk < 16; kk++) {
            float4 a0 = *(const float4*)&sm.a.XsT[kk][8 * ty];
            float4 a1 = *(const float4*)&sm.a.XsT[kk][8 * ty + 4];
            uint64_t B0 = *(const uint64_t*)&sm.a.Ws[kk][4 * tx];
            uint64_t B1 = *(const uint64_t*)&sm.a.Ws[kk][4 * tx + 2];
            uint64_t B2 = *(const uint64_t*)&sm.a.Ws[kk][64 + 4 * tx];
            uint64_t B3 = *(const uint64_t*)&sm.a.Ws[kk][64 + 4 * tx + 2];
            float av[8] = {a0.x, a0.y, a0.z, a0.w, a1.x, a1.y, a1.z, a1.w};
            #pragma unroll
            for (int i = 0; i < 8; i++) {
                uint64_t A = pack2(av[i], av[i]);
                fma2(acc[i][0], A, B0);
                fma2(acc[i][1], A, B1);
                fma2(acc[i][2], A, B2);
                fma2(acc[i][3], A, B3);
            }
        }
        __syncthreads();
    }

    #pragma unroll
    for (int i = 0; i < 8; i++) {
        int r = 8 * ty + i;
        float2 f;
        f = unpk(acc[i][0]);
        sm.Hs[r][4 * tx + 0]      = fmaxf(f.x + gcs[4 * tx + 0], 0.f);
        sm.Hs[r][4 * tx + 1]      = fmaxf(f.y + gcs[4 * tx + 1], 0.f);
        f = unpk(acc[i][1]);
        sm.Hs[r][4 * tx + 2]      = fmaxf(f.x + gcs[4 * tx + 2], 0.f);
        sm.Hs[r][4 * tx + 3]      = fmaxf(f.y + gcs[4 * tx + 3], 0.f);
        f = unpk(acc[i][2]);
        sm.Hs[r][64 + 4 * tx + 0] = fmaxf(f.x + gcs[64 + 4 * tx + 0], 0.f);
        sm.Hs[r][64 + 4 * tx + 1] = fmaxf(f.y + gcs[64 + 4 * tx + 1], 0.f);
        f = unpk(acc[i][3]);
        sm.Hs[r][64 + 4 * tx + 2] = fmaxf(f.x + gcs[64 + 4 * tx + 2], 0.f);
        sm.Hs[r][64 + 4 * tx + 3] = fmaxf(f.y + gcs[64 + 4 * tx + 3], 0.f);
    }
    __syncthreads();

    const int rg = t >> 2;
    const int m0 = 6 * (t & 3);
    uint64_t c2[2][3];
    #pragma unroll
    for (int i = 0; i < 2; i++)
        #pragma unroll
        for (int j = 0; j < 3; j++) c2[i][j] = 0ull;

    #pragma unroll 4
    for (int k = 0; k < 128; k++) {
        uint64_t w0 = *(const uint64_t*)&W2s[k * 24 + m0];
        uint64_t w1 = *(const uint64_t*)&W2s[k * 24 + m0 + 2];
        uint64_t w2 = *(const uint64_t*)&W2s[k * 24 + m0 + 4];
        float h0 = sm.Hs[2 * rg][k];
        float h1 = sm.Hs[2 * rg + 1][k];
        uint64_t H0 = pack2(h0, h0), H1 = pack2(h1, h1);
        fma2(c2[0][0], H0, w0); fma2(c2[0][1], H0, w1); fma2(c2[0][2], H0, w2);
        fma2(c2[1][0], H1, w0); fma2(c2[1][1], H1, w1); fma2(c2[1][2], H1, w2);
    }

    #pragma unroll
    for (int rr = 0; rr < 2; rr++) {
        int r = 2 * rg + rr;
        bool valid = nodes[r] >= 0;
        long gbase = (long)(row0 + r) * 24 + m0;
        #pragma unroll
        for (int j = 0; j < 3; j++) {
            float2 f = unpk(c2[rr][j]);
            long o = gbase + 2 * j;
            out[o]     = (valid && read_mask(move_mask, o, mode))     ? f.x + b2s[m0 + 2 * j]     : NEG;
            out[o + 1] = (valid && read_mask(move_mask, o + 1, mode)) ? f.y + b2s[m0 + 2 * j + 1] : NEG;
        }
    }
}

// ---------------------------------------------------------------------------
// heads: grid (B, 2). y=0: Docking. y=1: Maneuver + ActionType.
// ---------------------------------------------------------------------------
__global__ __launch_bounds__(128) void heads_kernel(
    const float* __restrict__ nodef, const float* __restrict__ gf,
    const int* __restrict__ atm, const void* __restrict__ dvm, const void* __restrict__ mvm,
    const float* __restrict__ at_W1, const float* __restrict__ at_b1,
    const float* __restrict__ at_W2, const float* __restrict__ at_b2,
    const float* __restrict__ dk_W1, const float* __restrict__ dk_b1,
    const float* __restrict__ dk_W2, const float* __restrict__ dk_b2,
    const float* __restrict__ dk_W3, const float* __restrict__ dk_b3,
    const float* __restrict__ mn_W1, const float* __restrict__ mn_b1,
    const float* __restrict__ mn_W2, const float* __restrict__ mn_b2,
    float* __restrict__ out_at, float* __restrict__ out_dock, float* __restrict__ out_man)
{
    __shared__ float gf8[G_][128];
    __shared__ float gl[128];
    __shared__ int   gid[G_];

    const int b = blockIdx.x, t = threadIdx.x;
    const int mode = mask_mode(atm);

    if (t < G_) gid[t] = d_group_node[b * G_ + t];
    gl[t] = gf[b * 128 + t];
    __syncthreads();
    #pragma unroll
    for (int i = 0; i < 8; i++) {
        int idx = t + i * 128;
        int g = idx >> 7, c = idx & 127;
        int n = gid[g];
        gf8[g][c] = (n >= 0) ? __ldg(nodef + (size_t)n * 128 + c) : 0.f;
    }
    __syncthreads();

    if (blockIdx.y == 0) {
        // ================= DOCKING =================
        __shared__ float uu[G_][128], vv[G_][128], ww[128];
        __shared__ float W2s[128 * 64];
        __shared__ float W3s[64];

        // stage dk_W2 (32KB) once
        #pragma unroll
        for (int i = 0; i < 64; i++) W2s[t + i * 128] = __ldg(dk_W2 + t + i * 128);
        if (t < 64) W3s[t] = __ldg(dk_W3 + t);

        // hidden pass: u/v per group, w per batch
        {
            float ua[G_], va[G_];
            #pragma unroll
            for (int g = 0; g < G_; g++) { ua[g] = 0.f; va[g] = 0.f; }
            float wv = __ldg(dk_b1 + t);
            #pragma unroll 2
            for (int k = 0; k < 128; k++) {
                float wa = __ldg(dk_W1 + k * 128 + t);
                float wb = __ldg(dk_W1 + (128 + k) * 128 + t);
                float wc = __ldg(dk_W1 + (256 + k) * 128 + t);
                #pragma unroll
                for (int g = 0; g < G_; g++) {
                    float x = gf8[g][k];
                    ua[g] = fmaf(x, wa, ua[g]);
                    va[g] = fmaf(x, wb, va[g]);
                }
                wv = fmaf(gl[k], wc, wv);
            }
            #pragma unroll
            for (int g = 0; g < G_; g++) { uu[g][t] = ua[g]; vv[g][t] = va[g]; }
            ww[t] = wv;
        }
        __syncthreads();

        // pair loop: warp w owns pairs 7w..7w+6, 2 pairs per round, no block sync
        const int wp = t >> 5, lane = t & 31;
        const float b2a = __ldg(dk_b2 + lane);
        const float b2b = __ldg(dk_b2 + lane + 32);
        const float b3v = __ldg(dk_b3);
        const float w3a = W3s[lane], w3b = W3s[lane + 32];

        for (int pb = 0; pb < 7; pb += 2) {
            const int p0 = 7 * wp + pb;
            const bool has1 = (pb + 1) < 7;
            const int p1 = has1 ? p0 + 1 : p0;
            const int i0 = c_IU[p0], j0 = c_JU[p0];
            const int i1 = c_IU[p1], j1 = c_JU[p1];
            float s0a = 0.f, s0b = 0.f, s1a = 0.f, s1b = 0.f;
            #pragma unroll 4
            for (int k = 0; k < 128; k++) {
                float wk = ww[k];
                float h0 = fmaxf(uu[i0][k] + vv[j0][k] + wk, 0.f);
                float h1 = fmaxf(uu[i1][k] + vv[j1][k] + wk, 0.f);
                float w2a = W2s[k * 64 + lane];
                float w2b = W2s[k * 64 + lane + 32];
                s0a = fmaf(h0, w2a, s0a);
                s0b = fmaf(h0, w2b, s0b);
                s1a = fmaf(h1, w2a, s1a);
                s1b = fmaf(h1, w2b, s1b);
            }
            float c0 = fmaxf(s0a + b2a, 0.f) * w3a + fmaxf(s0b + b2b, 0.f) * w3b;
            float c1 = fmaxf(s1a + b2a, 0.f) * w3a + fmaxf(s1b + b2b, 0.f) * w3b;
            #pragma unroll
            for (int off = 16; off; off >>= 1) {
                c0 += __shfl_down_sync(0xffffffffu, c0, off);
                c1 += __shfl_down_sync(0xffffffffu, c1, off);
            }
            if (lane == 0) {
                bool ok0 = read_mask(dvm, b * P_ + p0, mode) && gid[i0] >= 0 && gid[j0] >= 0;
                out_dock[b * P_ + p0] = ok0 ? (c0 + b3v) : NEG;
                if (has1) {
                    bool ok1 = read_mask(dvm, b * P_ + p1, mode) && gid[i1] >= 0 && gid[j1] >= 0;
                    out_dock[b * P_ + p1] = ok1 ? (c1 + b3v) : NEG;
                }
            }
        }
    } else {
        // ================= MANEUVER + ACTION TYPE =================
        __shared__ float manH[G_][128];
        __shared__ float ath[64];
        __shared__ float W2m[128 * ND_];

        #pragma unroll
        for (int i = 0; i < ND_; i++) W2m[t + i * 128] = __ldg(mn_W2 + t + i * 128);

        {
            float ma[G_];
            #pragma unroll
            for (int g = 0; g < G_; g++) ma[g] = 0.f;
            float gcm = __ldg(mn_b1 + t);
            float av = (t < 64) ? __ldg(at_b1 + t) : 0.f;
            #pragma unroll 2
            for (int k = 0; k < 128; k++) {
                float wa  = __ldg(mn_W1 + k * 128 + t);
                float wb  = __ldg(mn_W1 + (128 + k) * 128 + t);
                float gk  = gl[k];
                #pragma unroll
                for (int g = 0; g < G_; g++) ma[g] = fmaf(gf8[g][k], wa, ma[g]);
                gcm = fmaf(gk, wb, gcm);
                if (t < 64) av = fmaf(gk, __ldg(at_W1 + k * 64 + t), av);
            }
            #pragma unroll
            for (int g = 0; g < G_; g++) manH[g][t] = fmaxf(ma[g] + gcm, 0.f);
            if (t < 64) ath[t] = fmaxf(av, 0.f);
        }
        __syncthreads();

        if (t < G_ * ND_) {
            int g = t / ND_, d = t - g * ND_;
            float s = __ldg(mn_b2 + d);
            #pragma unroll 8
            for (int k = 0; k < 128; k++) s = fmaf(manH[g][k], W2m[k * ND_ + d], s);
            bool ok = (gid[g] >= 0) && read_mask(mvm, b * G_ * ND_ + t, mode);
            out_man[b * G_ * ND_ + t] = ok ? s : NEG;
        } else if (t >= 64 && t < 64 + AT_) {
            int a = t - 64;
            float s = __ldg(at_b2 + a);
            #pragma unroll 8
            for (int k = 0; k < 64; k++) s = fmaf(ath[k], __ldg(at_W2 + k * AT_ + a), s);
            out_at[b * AT_ + a] = read_mask(atm, b * AT_ + a, mode) ? s : NEG;
        }
    }
}

// ---------------------------------------------------------------------------
extern "C" void kernel_launch(void* const* d_in, const int* in_sizes, int n_in,
                              void* d_out, int out_size) {
    const float* nodef      = (const float*)d_in[0];
    const float* gf         = (const float*)d_in[1];
    const int*   atm        = (const int*)d_in[2];
    const void*  cube_mask  = d_in[3];
    const void*  group_mask = d_in[4];
    /* d_in[5] = batch (unused; segments contiguous) */
    const void*  move_mask  = d_in[6];
    const void*  dvm        = d_in[7];
    const void*  mvm        = d_in[8];
    const float* at_W1 = (const float*)d_in[9];
    const float* at_b1 = (const float*)d_in[10];
    const float* at_W2 = (const float*)d_in[11];
    const float* at_b2 = (const float*)d_in[12];
    const float* cm_W1 = (const float*)d_in[13];
    const float* cm_b1 = (const float*)d_in[14];
    const float* cm_W2 = (const float*)d_in[15];
    const float* cm_b2 = (const float*)d_in[16];
    const float* dk_W1 = (const float*)d_in[17];
    const float* dk_b1 = (const float*)d_in[18];
    const float* dk_W2 = (const float*)d_in[19];
    const float* dk_b2 = (const float*)d_in[20];
    const float* dk_W3 = (const float*)d_in[21];
    const float* dk_b3 = (const float*)d_in[22];
    const float* mn_W1 = (const float*)d_in[23];
    const float* mn_b1 = (const float*)d_in[24];
    const float* mn_W2 = (const float*)d_in[25];
    const float* mn_b2 = (const float*)d_in[26];

    float* out      = (float*)d_out;
    float* out_at   = out;
    float* out_cube = out + (size_t)B_ * AT_;
    float* out_dock = out_cube + (size_t)B_ * MAXC * M_;
    float* out_man  = out_dock + (size_t)B_ * P_;

    setup_kernel<<<B_, 160>>>(gf, cm_W1, cm_b1, cube_mask, group_mask, atm);
    heads_kernel<<<dim3(B_, 2), 128>>>(nodef, gf, atm, dvm, mvm,
                                       at_W1, at_b1, at_W2, at_b2,
                                       dk_W1, dk_b1, dk_W2, dk_b2, dk_W3, dk_b3,
                                       mn_W1, mn_b1, mn_W2, mn_b2,
                                       out_at, out_dock, out_man);
    cube_kernel<<<(B_ * MAXC) / 64, 128>>>(nodef, cm_W1, cm_W2, cm_b2, move_mask, atm, out_cube);
}

// round 6
// speedup vs baseline: 2.6561x; 1.2663x over previous
#include <cuda_runtime.h>
#include <stdint.h>

#define NEG (-1e9f)
constexpr int B_   = 128;
constexpr int NPG  = 1024;
constexpr int M_   = 24;
constexpr int MAXC = 512;
constexpr int G_   = 8;
constexpr int ND_  = 7;
constexpr int AT_  = 5;
constexpr int P_   = 28;

__device__ int   d_cube_node[B_ * MAXC];
__device__ int   d_group_node[B_ * G_];
__device__ float d_cm_gc[B_ * 128];

__constant__ int c_IU[P_] = {0,0,0,0,0,0,0,1,1,1,1,1,1,2,2,2,2,2,3,3,3,3,4,4,4,5,5,6};
__constant__ int c_JU[P_] = {1,2,3,4,5,6,7,2,3,4,5,6,7,3,4,5,6,7,4,5,6,7,5,6,7,6,7,7};

__device__ __forceinline__ int mask_mode(const int* __restrict__ atm) {
    int v = __ldg(atm);
    if (v == 1) return 1;
    if (v == 0x3F800000) return 2;
    return 0;
}
__device__ __forceinline__ bool read_mask(const void* p, long i, int mode) {
    if (mode == 1) return ((const int*)p)[i] != 0;
    if (mode == 2) return ((const float*)p)[i] != 0.f;
    return ((const uint8_t*)p)[i] != 0;
}

// -------- f32x2 packed helpers (sm_103a) --------
__device__ __forceinline__ uint64_t pack2(float x, float y) {
    uint64_t r; asm("mov.b64 %0, {%1, %2};" : "=l"(r) : "f"(x), "f"(y)); return r;
}
__device__ __forceinline__ void fma2(uint64_t& d, uint64_t a, uint64_t b) {
    asm("fma.rn.f32x2 %0, %1, %2, %0;" : "+l"(d) : "l"(a), "l"(b));
}
__device__ __forceinline__ float2 unpk(uint64_t v) {
    float2 f; asm("mov.b64 {%0, %1}, %2;" : "=f"(f.x), "=f"(f.y) : "l"(v)); return f;
}

// ---------------------------------------------------------------------------
// setup: warps 0-3 gcontrib (k-split, float4), warps 4-7 parallel index scan
// ---------------------------------------------------------------------------
__global__ __launch_bounds__(256) void setup_kernel(
    const float* __restrict__ gf,
    const float* __restrict__ cmW1, const float* __restrict__ cmb1,
    const void* __restrict__ cube_mask, const void* __restrict__ group_mask,
    const int* __restrict__ atm)
{
    const int b = blockIdx.x, t = threadIdx.x;
    const int w = t >> 5, lane = t & 31;
    const int mode = mask_mode(atm);
    __shared__ float g[128];
    __shared__ float sred[4][128];
    __shared__ int wtc[4], wtg[4], stc, stg;

    if (t < 128) g[t] = gf[b * 128 + t];
    __syncthreads();

    unsigned cm8 = 0, gm8 = 0;
    int cex = 0, gex = 0;

    if (w < 4) {
        const float4* W4 = (const float4*)cmW1;
        float4 a = make_float4(0.f, 0.f, 0.f, 0.f);
        #pragma unroll
        for (int kk = 0; kk < 32; kk++) {
            int k = 32 * w + kk;
            float4 wv = __ldg(&W4[(128 + k) * 32 + lane]);
            float gk = g[k];
            a.x = fmaf(gk, wv.x, a.x);
            a.y = fmaf(gk, wv.y, a.y);
            a.z = fmaf(gk, wv.z, a.z);
            a.w = fmaf(gk, wv.w, a.w);
        }
        *(float4*)&sred[w][4 * lane] = a;
    } else if (mode == 1) {
        const int w4 = w - 4;
        const int4* cm4 = (const int4*)cube_mask + b * 256 + w4 * 64 + lane * 2;
        const int4* gm4 = (const int4*)group_mask + b * 256 + w4 * 64 + lane * 2;
        int4 c0 = __ldg(cm4), c1 = __ldg(cm4 + 1);
        int4 g0 = __ldg(gm4), g1 = __ldg(gm4 + 1);
        cm8 = (c0.x != 0) | ((c0.y != 0) << 1) | ((c0.z != 0) << 2) | ((c0.w != 0) << 3)
            | ((c1.x != 0) << 4) | ((c1.y != 0) << 5) | ((c1.z != 0) << 6) | ((c1.w != 0) << 7);
        gm8 = (g0.x != 0) | ((g0.y != 0) << 1) | ((g0.z != 0) << 2) | ((g0.w != 0) << 3)
            | ((g1.x != 0) << 4) | ((g1.y != 0) << 5) | ((g1.z != 0) << 6) | ((g1.w != 0) << 7);
        int cs = __popc(cm8), gs = __popc(gm8);
        int csi = cs, gsi = gs;
        #pragma unroll
        for (int off = 1; off < 32; off <<= 1) {
            int v1 = __shfl_up_sync(0xffffffffu, csi, off);
            int v2 = __shfl_up_sync(0xffffffffu, gsi, off);
            if (lane >= off) { csi += v1; gsi += v2; }
        }
        cex = csi - cs; gex = gsi - gs;
        if (lane == 31) { wtc[w4] = csi; wtg[w4] = gsi; }
    } else if (w == 4) {
        // dtype fallback: serial warp scan
        int cc = 0, gc = 0;
        for (int c = 0; c < NPG; c += 32) {
            long node = (long)b * NPG + c + lane;
            bool cm = read_mask(cube_mask, node, mode);
            bool gm = read_mask(group_mask, node, mode);
            unsigned cb = __ballot_sync(0xffffffffu, cm);
            unsigned gb = __ballot_sync(0xffffffffu, gm);
            unsigned lt = (1u << lane) - 1u;
            if (cm) { int p = cc + __popc(cb & lt); if (p < MAXC) d_cube_node[b * MAXC + p] = (int)node; }
            if (gm) { int p = gc + __popc(gb & lt); if (p < G_)   d_group_node[b * G_ + p] = (int)node; }
            cc += __popc(cb);
            gc += __popc(gb);
        }
        if (lane == 0) { stc = cc; stg = gc; }
    }
    __syncthreads();

    if (t < 128)
        d_cm_gc[b * 128 + t] = __ldg(cmb1 + t) +
            ((sred[0][t] + sred[1][t]) + (sred[2][t] + sred[3][t]));

    int tc, tg;
    if (mode == 1) {
        tc = wtc[0] + wtc[1] + wtc[2] + wtc[3];
        tg = wtg[0] + wtg[1] + wtg[2] + wtg[3];
        if (w >= 4) {
            const int w4 = w - 4;
            int cbase = 0, gbase = 0;
            #pragma unroll
            for (int i = 0; i < 4; i++) if (i < w4) { cbase += wtc[i]; gbase += wtg[i]; }
            const int nb = b * NPG + w4 * 256 + lane * 8;
            #pragma unroll
            for (int j = 0; j < 8; j++) {
                if ((cm8 >> j) & 1) {
                    int p = cbase + cex + __popc(cm8 & ((1u << j) - 1u));
                    if (p < MAXC) d_cube_node[b * MAXC + p] = nb + j;
                }
                if ((gm8 >> j) & 1) {
                    int p = gbase + gex + __popc(gm8 & ((1u << j) - 1u));
                    if (p < G_) d_group_node[b * G_ + p] = nb + j;
                }
            }
        }
    } else {
        tc = stc; tg = stg;
    }
    for (int p = tc + t; p < MAXC; p += 256) d_cube_node[b * MAXC + p] = -1;
    for (int p = tg + t; p < G_; p += 256)   d_group_node[b * G_ + p] = -1;
}

// ---------------------------------------------------------------------------
// mega kernel: blocks 0-127 docking, 128-255 maneuver+actiontype, 256+ cube
// ---------------------------------------------------------------------------
struct CubeP1 { float XsT[2][16][68]; float Ws[2][16][132]; };
struct CubeSM {
    union { CubeP1 p1; float Hs[64][132]; } u;
    float W2s[128 * 24];
    float b2s[24];
    float gcs[128];
    int   nodes[64];
};
struct DockSM {
    float gf8[G_][128];
    float gl[128];
    float uu[G_][128], vv[G_][128], ww[128];
    float W2s[128 * 64];
    float W3s[64];
    int   gid[G_];
};
struct ManSM {
    float gf8[G_][128];
    float gl[128];
    float manH[G_][128];
    float ath[64];
    float W2m[128 * ND_];
    int   gid[G_];
};
union MegaSM { CubeSM c; DockSM d; ManSM m; };

__global__ __launch_bounds__(128) void mega_kernel(
    const float* __restrict__ nodef, const float* __restrict__ gf,
    const int* __restrict__ atm, const void* __restrict__ move_mask,
    const void* __restrict__ dvm, const void* __restrict__ mvm,
    const float* __restrict__ cm_W1, const float* __restrict__ cm_W2, const float* __restrict__ cm_b2,
    const float* __restrict__ at_W1, const float* __restrict__ at_b1,
    const float* __restrict__ at_W2, const float* __restrict__ at_b2,
    const float* __restrict__ dk_W1, const float* __restrict__ dk_b1,
    const float* __restrict__ dk_W2, const float* __restrict__ dk_b2,
    const float* __restrict__ dk_W3, const float* __restrict__ dk_b3,
    const float* __restrict__ mn_W1, const float* __restrict__ mn_b1,
    const float* __restrict__ mn_W2, const float* __restrict__ mn_b2,
    float* __restrict__ out_at, float* __restrict__ out_cube,
    float* __restrict__ out_dock, float* __restrict__ out_man)
{
    __shared__ MegaSM sm;
    const int t = threadIdx.x;
    const int mode = mask_mode(atm);

    if (blockIdx.x >= 256) {
        // ===================== CUBE =====================
        CubeSM& C = sm.c;
        const int row0 = (blockIdx.x - 256) * 64;
        const int b = row0 >> 9;
        const int tx = t & 15, ty = t >> 4;

        if (t < 64) C.nodes[t] = d_cube_node[row0 + t];
        C.gcs[t] = d_cm_gc[b * 128 + t];
        #pragma unroll
        for (int i = 0; i < 24; i++) C.W2s[t + i * 128] = __ldg(cm_W2 + t + i * 128);
        if (t < 24) C.b2s[t] = __ldg(cm_b2 + t);
        __syncthreads();

        // prologue: chunk 0 -> buffer 0
        float xr[8], wr[16];
        #pragma unroll
        for (int i = 0; i < 8; i++) {
            int lin = t + i * 128, r = lin >> 4, c = lin & 15;
            int nd = C.nodes[r];
            xr[i] = (nd >= 0) ? __ldg(nodef + (size_t)nd * 128 + c) : 0.f;
        }
        #pragma unroll
        for (int i = 0; i < 16; i++) {
            int lin = t + i * 128, r = lin >> 7, c = lin & 127;
            wr[i] = __ldg(cm_W1 + (size_t)r * 128 + c);
        }
        #pragma unroll
        for (int i = 0; i < 8; i++) {
            int lin = t + i * 128, r = lin >> 4, c = lin & 15;
            C.u.p1.XsT[0][c][r] = xr[i];
        }
        #pragma unroll
        for (int i = 0; i < 16; i++) {
            int lin = t + i * 128, r = lin >> 7, c = lin & 127;
            C.u.p1.Ws[0][r][c] = wr[i];
        }
        __syncthreads();

        uint64_t acc[8][4];
        #pragma unroll
        for (int i = 0; i < 8; i++)
            #pragma unroll
            for (int j = 0; j < 4; j++) acc[i][j] = 0ull;

        #pragma unroll
        for (int ch = 0; ch < 8; ch++) {
            const int cur = ch & 1;
            if (ch < 7) {                      // prefetch next chunk into regs
                const int k0 = (ch + 1) * 16;
                #pragma unroll
                for (int i = 0; i < 8; i++) {
                    int lin = t + i * 128, r = lin >> 4, c = lin & 15;
                    int nd = C.nodes[r];
                    xr[i] = (nd >= 0) ? __ldg(nodef + (size_t)nd * 128 + k0 + c) : 0.f;
                }
                #pragma unroll
                for (int i = 0; i < 16; i++) {
                    int lin = t + i * 128, r = lin >> 7, c = lin & 127;
                    wr[i] = __ldg(cm_W1 + (size_t)(k0 + r) * 128 + c);
                }
            }
            #pragma unroll
            for (int kk = 0; kk < 16; kk++) {
                float4 a0 = *(const float4*)&C.u.p1.XsT[cur][kk][8 * ty];
                float4 a1 = *(const float4*)&C.u.p1.XsT[cur][kk][8 * ty + 4];
                ulonglong2 Bv0 = *(const ulonglong2*)&C.u.p1.Ws[cur][kk][4 * tx];
                ulonglong2 Bv1 = *(const ulonglong2*)&C.u.p1.Ws[cur][kk][64 + 4 * tx];
                float av[8] = {a0.x, a0.y, a0.z, a0.w, a1.x, a1.y, a1.z, a1.w};
                #pragma unroll
                for (int i = 0; i < 8; i++) {
                    uint64_t A = pack2(av[i], av[i]);
                    fma2(acc[i][0], A, Bv0.x);
                    fma2(acc[i][1], A, Bv0.y);
                    fma2(acc[i][2], A, Bv1.x);
                    fma2(acc[i][3], A, Bv1.y);
                }
            }
            if (ch < 7) {                      // store prefetched -> other buffer
                const int nxt = cur ^ 1;
                #pragma unroll
                for (int i = 0; i < 8; i++) {
                    int lin = t + i * 128, r = lin >> 4, c = lin & 15;
                    C.u.p1.XsT[nxt][c][r] = xr[i];
                }
                #pragma unroll
                for (int i = 0; i < 16; i++) {
                    int lin = t + i * 128, r = lin >> 7, c = lin & 127;
                    C.u.p1.Ws[nxt][r][c] = wr[i];
                }
            }
            __syncthreads();
        }

        // epilogue GEMM1: + gc, relu -> Hs (aliases p1; all reads done)
        #pragma unroll
        for (int i = 0; i < 8; i++) {
            int r = 8 * ty + i;
            float2 f;
            f = unpk(acc[i][0]);
            sm.c.u.Hs[r][4 * tx + 0]      = fmaxf(f.x + C.gcs[4 * tx + 0], 0.f);
            sm.c.u.Hs[r][4 * tx + 1]      = fmaxf(f.y + C.gcs[4 * tx + 1], 0.f);
            f = unpk(acc[i][1]);
            sm.c.u.Hs[r][4 * tx + 2]      = fmaxf(f.x + C.gcs[4 * tx + 2], 0.f);
            sm.c.u.Hs[r][4 * tx + 3]      = fmaxf(f.y + C.gcs[4 * tx + 3], 0.f);
            f = unpk(acc[i][2]);
            sm.c.u.Hs[r][64 + 4 * tx + 0] = fmaxf(f.x + C.gcs[64 + 4 * tx + 0], 0.f);
            sm.c.u.Hs[r][64 + 4 * tx + 1] = fmaxf(f.y + C.gcs[64 + 4 * tx + 1], 0.f);
            f = unpk(acc[i][3]);
            sm.c.u.Hs[r][64 + 4 * tx + 2] = fmaxf(f.x + C.gcs[64 + 4 * tx + 2], 0.f);
            sm.c.u.Hs[r][64 + 4 * tx + 3] = fmaxf(f.y + C.gcs[64 + 4 * tx + 3], 0.f);
        }
        __syncthreads();

        // GEMM2: 64x128 @ 128x24
        const int rg = t >> 2;
        const int m0 = 6 * (t & 3);
        uint64_t c2[2][3];
        #pragma unroll
        for (int i = 0; i < 2; i++)
            #pragma unroll
            for (int j = 0; j < 3; j++) c2[i][j] = 0ull;

        #pragma unroll 4
        for (int k = 0; k < 128; k++) {
            uint64_t w0 = *(const uint64_t*)&C.W2s[k * 24 + m0];
            uint64_t w1 = *(const uint64_t*)&C.W2s[k * 24 + m0 + 2];
            uint64_t w2 = *(const uint64_t*)&C.W2s[k * 24 + m0 + 4];
            float h0 = sm.c.u.Hs[2 * rg][k];
            float h1 = sm.c.u.Hs[2 * rg + 1][k];
            uint64_t H0 = pack2(h0, h0), H1 = pack2(h1, h1);
            fma2(c2[0][0], H0, w0); fma2(c2[0][1], H0, w1); fma2(c2[0][2], H0, w2);
            fma2(c2[1][0], H1, w0); fma2(c2[1][1], H1, w1); fma2(c2[1][2], H1, w2);
        }

        #pragma unroll
        for (int rr = 0; rr < 2; rr++) {
            int r = 2 * rg + rr;
            bool valid = C.nodes[r] >= 0;
            long gbase = (long)(row0 + r) * 24 + m0;
            #pragma unroll
            for (int j = 0; j < 3; j++) {
                float2 f = unpk(c2[rr][j]);
                long o = gbase + 2 * j;
                out_cube[o]     = (valid && read_mask(move_mask, o, mode))     ? f.x + C.b2s[m0 + 2 * j]     : NEG;
                out_cube[o + 1] = (valid && read_mask(move_mask, o + 1, mode)) ? f.y + C.b2s[m0 + 2 * j + 1] : NEG;
            }
        }
        return;
    }

    // ===================== HEADS =====================
    const int b = blockIdx.x & 127;
    if (blockIdx.x < 128) {
        // ---------- DOCKING ----------
        DockSM& D = sm.d;
        if (t < G_) D.gid[t] = d_group_node[b * G_ + t];
        D.gl[t] = gf[b * 128 + t];
        __syncthreads();
        #pragma unroll
        for (int i = 0; i < 8; i++) {
            int idx = t + i * 128;
            int g = idx >> 7, c = idx & 127;
            int n = D.gid[g];
            D.gf8[g][c] = (n >= 0) ? __ldg(nodef + (size_t)n * 128 + c) : 0.f;
        }
        __syncthreads();

        #pragma unroll
        for (int i = 0; i < 64; i++) D.W2s[t + i * 128] = __ldg(dk_W2 + t + i * 128);
        if (t < 64) D.W3s[t] = __ldg(dk_W3 + t);

        {
            float ua[G_], va[G_];
            #pragma unroll
            for (int g = 0; g < G_; g++) { ua[g] = 0.f; va[g] = 0.f; }
            float wv = __ldg(dk_b1 + t);
            #pragma unroll 4
            for (int k = 0; k < 128; k++) {
                float wa = __ldg(dk_W1 + k * 128 + t);
                float wb = __ldg(dk_W1 + (128 + k) * 128 + t);
                float wc = __ldg(dk_W1 + (256 + k) * 128 + t);
                #pragma unroll
                for (int g = 0; g < G_; g++) {
                    float x = D.gf8[g][k];
                    ua[g] = fmaf(x, wa, ua[g]);
                    va[g] = fmaf(x, wb, va[g]);
                }
                wv = fmaf(D.gl[k], wc, wv);
            }
            #pragma unroll
            for (int g = 0; g < G_; g++) { D.uu[g][t] = ua[g]; D.vv[g][t] = va[g]; }
            D.ww[t] = wv;
        }
        __syncthreads();

        const int wp = t >> 5, lane = t & 31;
        const float b2a = __ldg(dk_b2 + lane);
        const float b2b = __ldg(dk_b2 + lane + 32);
        const float b3v = __ldg(dk_b3);
        const float w3a = D.W3s[lane], w3b = D.W3s[lane + 32];

        for (int pb = 0; pb < 7; pb += 2) {
            const int p0 = 7 * wp + pb;
            const bool has1 = (pb + 1) < 7;
            const int p1 = has1 ? p0 + 1 : p0;
            const int i0 = c_IU[p0], j0 = c_JU[p0];
            const int i1 = c_IU[p1], j1 = c_JU[p1];
            float s0a = 0.f, s0b = 0.f, s1a = 0.f, s1b = 0.f;
            #pragma unroll 4
            for (int k = 0; k < 128; k++) {
                float wk = D.ww[k];
                float h0 = fmaxf(D.uu[i0][k] + D.vv[j0][k] + wk, 0.f);
                float h1 = fmaxf(D.uu[i1][k] + D.vv[j1][k] + wk, 0.f);
                float w2a = D.W2s[k * 64 + lane];
                float w2b = D.W2s[k * 64 + lane + 32];
                s0a = fmaf(h0, w2a, s0a);
                s0b = fmaf(h0, w2b, s0b);
                s1a = fmaf(h1, w2a, s1a);
                s1b = fmaf(h1, w2b, s1b);
            }
            float c0 = fmaxf(s0a + b2a, 0.f) * w3a + fmaxf(s0b + b2b, 0.f) * w3b;
            float c1 = fmaxf(s1a + b2a, 0.f) * w3a + fmaxf(s1b + b2b, 0.f) * w3b;
            #pragma unroll
            for (int off = 16; off; off >>= 1) {
                c0 += __shfl_down_sync(0xffffffffu, c0, off);
                c1 += __shfl_down_sync(0xffffffffu, c1, off);
            }
            if (lane == 0) {
                bool ok0 = read_mask(dvm, b * P_ + p0, mode) && D.gid[i0] >= 0 && D.gid[j0] >= 0;
                out_dock[b * P_ + p0] = ok0 ? (c0 + b3v) : NEG;
                if (has1) {
                    bool ok1 = read_mask(dvm, b * P_ + p1, mode) && D.gid[i1] >= 0 && D.gid[j1] >= 0;
                    out_dock[b * P_ + p1] = ok1 ? (c1 + b3v) : NEG;
                }
            }
        }
    } else {
        // ---------- MANEUVER + ACTION TYPE ----------
        ManSM& Mn = sm.m;
        if (t < G_) Mn.gid[t] = d_group_node[b * G_ + t];
        Mn.gl[t] = gf[b * 128 + t];
        __syncthreads();
        #pragma unroll
        for (int i = 0; i < 8; i++) {
            int idx = t + i * 128;
            int g = idx >> 7, c = idx & 127;
            int n = Mn.gid[g];
            Mn.gf8[g][c] = (n >= 0) ? __ldg(nodef + (size_t)n * 128 + c) : 0.f;
        }
        __syncthreads();

        #pragma unroll
        for (int i = 0; i < ND_; i++) Mn.W2m[t + i * 128] = __ldg(mn_W2 + t + i * 128);

        {
            float ma[G_];
            #pragma unroll
            for (int g = 0; g < G_; g++) ma[g] = 0.f;
            float gcm = __ldg(mn_b1 + t);
            float av = (t < 64) ? __ldg(at_b1 + t) : 0.f;
            #pragma unroll 4
            for (int k = 0; k < 128; k++) {
                float wa = __ldg(mn_W1 + k * 128 + t);
                float wb = __ldg(mn_W1 + (128 + k) * 128 + t);
                float gk = Mn.gl[k];
                #pragma unroll
                for (int g = 0; g < G_; g++) ma[g] = fmaf(Mn.gf8[g][k], wa, ma[g]);
                gcm = fmaf(gk, wb, gcm);
                if (t < 64) av = fmaf(gk, __ldg(at_W1 + k * 64 + t), av);
            }
            #pragma unroll
            for (int g = 0; g < G_; g++) Mn.manH[g][t] = fmaxf(ma[g] + gcm, 0.f);
            if (t < 64) Mn.ath[t] = fmaxf(av, 0.f);
        }
        __syncthreads();

        if (t < G_ * ND_) {
            int g = t / ND_, d = t - g * ND_;
            float s = __ldg(mn_b2 + d);
            #pragma unroll 8
            for (int k = 0; k < 128; k++) s = fmaf(Mn.manH[g][k], Mn.W2m[k * ND_ + d], s);
            bool ok = (Mn.gid[g] >= 0) && read_mask(mvm, b * G_ * ND_ + t, mode);
            out_man[b * G_ * ND_ + t] = ok ? s : NEG;
        } else if (t >= 64 && t < 64 + AT_) {
            int a = t - 64;
            float s = __ldg(at_b2 + a);
            #pragma unroll 8
            for (int k = 0; k < 64; k++) s = fmaf(Mn.ath[k], __ldg(at_W2 + k * AT_ + a), s);
            out_at[b * AT_ + a] = read_mask(atm, b * AT_ + a, mode) ? s : NEG;
        }
    }
}

// ---------------------------------------------------------------------------
extern "C" void kernel_launch(void* const* d_in, const int* in_sizes, int n_in,
                              void* d_out, int out_size) {
    const float* nodef      = (const float*)d_in[0];
    const float* gf         = (const float*)d_in[1];
    const int*   atm        = (const int*)d_in[2];
    const void*  cube_mask  = d_in[3];
    const void*  group_mask = d_in[4];
    /* d_in[5] = batch (unused; segments contiguous) */
    const void*  move_mask  = d_in[6];
    const void*  dvm        = d_in[7];
    const void*  mvm        = d_in[8];
    const float* at_W1 = (const float*)d_in[9];
    const float* at_b1 = (const float*)d_in[10];
    const float* at_W2 = (const float*)d_in[11];
    const float* at_b2 = (const float*)d_in[12];
    const float* cm_W1 = (const float*)d_in[13];
    const float* cm_b1 = (const float*)d_in[14];
    const float* cm_W2 = (const float*)d_in[15];
    const float* cm_b2 = (const float*)d_in[16];
    const float* dk_W1 = (const float*)d_in[17];
    const float* dk_b1 = (const float*)d_in[18];
    const float* dk_W2 = (const float*)d_in[19];
    const float* dk_b2 = (const float*)d_in[20];
    const float* dk_W3 = (const float*)d_in[21];
    const float* dk_b3 = (const float*)d_in[22];
    const float* mn_W1 = (const float*)d_in[23];
    const float* mn_b1 = (const float*)d_in[24];
    const float* mn_W2 = (const float*)d_in[25];
    const float* mn_b2 = (const float*)d_in[26];

    float* out      = (float*)d_out;
    float* out_at   = out;
    float* out_cube = out + (size_t)B_ * AT_;
    float* out_dock = out_cube + (size_t)B_ * MAXC * M_;
    float* out_man  = out_dock + (size_t)B_ * P_;

    setup_kernel<<<B_, 256>>>(gf, cm_W1, cm_b1, cube_mask, group_mask, atm);
    mega_kernel<<<256 + (B_ * MAXC) / 64, 128>>>(
        nodef, gf, atm, move_mask, dvm, mvm,
        cm_W1, cm_W2, cm_b2,
        at_W1, at_b1, at_W2, at_b2,
        dk_W1, dk_b1, dk_W2, dk_b2, dk_W3, dk_b3,
        mn_W1, mn_b1, mn_W2, mn_b2,
        out_at, out_cube, out_dock, out_man);
}

// round 8
// speedup vs baseline: 3.9595x; 1.4907x over previous
#include <cuda_runtime.h>
#include <cuda_bf16.h>
#include <stdint.h>

#define NEG (-1e9f)
constexpr int B_   = 128;
constexpr int NPG  = 1024;
constexpr int M_   = 24;
constexpr int MAXC = 512;
constexpr int G_   = 8;
constexpr int ND_  = 7;
constexpr int AT_  = 5;
constexpr int P_   = 28;

__device__ int   d_cube_node[B_ * MAXC];
__device__ int   d_group_node[B_ * G_];
__device__ float d_cm_gc[B_ * 128];

__constant__ int c_IU[P_] = {0,0,0,0,0,0,0,1,1,1,1,1,1,2,2,2,2,2,3,3,3,3,4,4,4,5,5,6};
__constant__ int c_JU[P_] = {1,2,3,4,5,6,7,2,3,4,5,6,7,3,4,5,6,7,4,5,6,7,5,6,7,6,7,7};

__device__ __forceinline__ int mask_mode(const int* __restrict__ atm) {
    int v = __ldg(atm);
    if (v == 1) return 1;
    if (v == 0x3F800000) return 2;
    return 0;
}
__device__ __forceinline__ bool read_mask(const void* p, long i, int mode) {
    if (mode == 1) return ((const int*)p)[i] != 0;
    if (mode == 2) return ((const float*)p)[i] != 0.f;
    return ((const uint8_t*)p)[i] != 0;
}

// bf16 mma.sync (sm_80+ baseline PTX -> HMMA on sm_103)
__device__ __forceinline__ void mma16816(float* c, uint32_t a0, uint32_t a1,
                                         uint32_t a2, uint32_t a3,
                                         uint32_t b0, uint32_t b1) {
    asm volatile(
        "mma.sync.aligned.m16n8k16.row.col.f32.bf16.bf16.f32 "
        "{%0,%1,%2,%3}, {%4,%5,%6,%7}, {%8,%9}, {%0,%1,%2,%3};"
        : "+f"(c[0]), "+f"(c[1]), "+f"(c[2]), "+f"(c[3])
        : "r"(a0), "r"(a1), "r"(a2), "r"(a3), "r"(b0), "r"(b1));
}
__device__ __forceinline__ uint32_t bf2(float x, float y) {
    __nv_bfloat162 p = __float22bfloat162_rn(make_float2(x, y));
    return *(uint32_t*)&p;
}

// ---------------------------------------------------------------------------
// setup: warps 0-3 gcontrib (k-split, float4), warps 4-7 parallel index scan
// ---------------------------------------------------------------------------
__global__ __launch_bounds__(256) void setup_kernel(
    const float* __restrict__ gf,
    const float* __restrict__ cmW1, const float* __restrict__ cmb1,
    const void* __restrict__ cube_mask, const void* __restrict__ group_mask,
    const int* __restrict__ atm)
{
    const int b = blockIdx.x, t = threadIdx.x;
    const int w = t >> 5, lane = t & 31;
    const int mode = mask_mode(atm);
    __shared__ float g[128];
    __shared__ float sred[4][128];
    __shared__ int wtc[4], wtg[4], stc, stg;

    if (t < 128) g[t] = gf[b * 128 + t];
    __syncthreads();

    unsigned cm8 = 0, gm8 = 0;
    int cex = 0, gex = 0;

    if (w < 4) {
        const float4* W4 = (const float4*)cmW1;
        float4 a = make_float4(0.f, 0.f, 0.f, 0.f);
        #pragma unroll
        for (int kk = 0; kk < 32; kk++) {
            int k = 32 * w + kk;
            float4 wv = __ldg(&W4[(128 + k) * 32 + lane]);
            float gk = g[k];
            a.x = fmaf(gk, wv.x, a.x);
            a.y = fmaf(gk, wv.y, a.y);
            a.z = fmaf(gk, wv.z, a.z);
            a.w = fmaf(gk, wv.w, a.w);
        }
        *(float4*)&sred[w][4 * lane] = a;
    } else if (mode == 1) {
        const int w4 = w - 4;
        const int4* cm4 = (const int4*)cube_mask + b * 256 + w4 * 64 + lane * 2;
        const int4* gm4 = (const int4*)group_mask + b * 256 + w4 * 64 + lane * 2;
        int4 c0 = __ldg(cm4), c1 = __ldg(cm4 + 1);
        int4 g0 = __ldg(gm4), g1 = __ldg(gm4 + 1);
        cm8 = (c0.x != 0) | ((c0.y != 0) << 1) | ((c0.z != 0) << 2) | ((c0.w != 0) << 3)
            | ((c1.x != 0) << 4) | ((c1.y != 0) << 5) | ((c1.z != 0) << 6) | ((c1.w != 0) << 7);
        gm8 = (g0.x != 0) | ((g0.y != 0) << 1) | ((g0.z != 0) << 2) | ((g0.w != 0) << 3)
            | ((g1.x != 0) << 4) | ((g1.y != 0) << 5) | ((g1.z != 0) << 6) | ((g1.w != 0) << 7);
        int cs = __popc(cm8), gs = __popc(gm8);
        int csi = cs, gsi = gs;
        #pragma unroll
        for (int off = 1; off < 32; off <<= 1) {
            int v1 = __shfl_up_sync(0xffffffffu, csi, off);
            int v2 = __shfl_up_sync(0xffffffffu, gsi, off);
            if (lane >= off) { csi += v1; gsi += v2; }
        }
        cex = csi - cs; gex = gsi - gs;
        if (lane == 31) { wtc[w4] = csi; wtg[w4] = gsi; }
    } else if (w == 4) {
        int cc = 0, gc = 0;
        for (int c = 0; c < NPG; c += 32) {
            long node = (long)b * NPG + c + lane;
            bool cm = read_mask(cube_mask, node, mode);
            bool gm = read_mask(group_mask, node, mode);
            unsigned cb = __ballot_sync(0xffffffffu, cm);
            unsigned gb = __ballot_sync(0xffffffffu, gm);
            unsigned lt = (1u << lane) - 1u;
            if (cm) { int p = cc + __popc(cb & lt); if (p < MAXC) d_cube_node[b * MAXC + p] = (int)node; }
            if (gm) { int p = gc + __popc(gb & lt); if (p < G_)   d_group_node[b * G_ + p] = (int)node; }
            cc += __popc(cb);
            gc += __popc(gb);
        }
        if (lane == 0) { stc = cc; stg = gc; }
    }
    __syncthreads();

    if (t < 128)
        d_cm_gc[b * 128 + t] = __ldg(cmb1 + t) +
            ((sred[0][t] + sred[1][t]) + (sred[2][t] + sred[3][t]));

    int tc, tg;
    if (mode == 1) {
        tc = wtc[0] + wtc[1] + wtc[2] + wtc[3];
        tg = wtg[0] + wtg[1] + wtg[2] + wtg[3];
        if (w >= 4) {
            const int w4 = w - 4;
            int cbase = 0, gbase = 0;
            #pragma unroll
            for (int i = 0; i < 4; i++) if (i < w4) { cbase += wtc[i]; gbase += wtg[i]; }
            const int nb = b * NPG + w4 * 256 + lane * 8;
            #pragma unroll
            for (int j = 0; j < 8; j++) {
                if ((cm8 >> j) & 1) {
                    int p = cbase + cex + __popc(cm8 & ((1u << j) - 1u));
                    if (p < MAXC) d_cube_node[b * MAXC + p] = nb + j;
                }
                if ((gm8 >> j) & 1) {
                    int p = gbase + gex + __popc(gm8 & ((1u << j) - 1u));
                    if (p < G_) d_group_node[b * G_ + p] = nb + j;
                }
            }
        }
    } else {
        tc = stc; tg = stg;
    }
    for (int p = tc + t; p < MAXC; p += 256) d_cube_node[b * MAXC + p] = -1;
    for (int p = tg + t; p < G_; p += 256)   d_group_node[b * G_ + p] = -1;
}

// ---------------------------------------------------------------------------
// mega kernel, 256 threads/block:
//   blocks 0-127 docking, 128-255 maneuver+AT, 256-767 cube (mma.sync bf16)
// cube dyn smem map (bytes):
//   Xs/Hs 0..34816 | Ws1 34816..69632 | Ws2 69632..76160
//   gcs 76160..76672 | b2s 76672..76768 | nodes 76768..77280
// ---------------------------------------------------------------------------
constexpr int SMEM_DYN = 77280;

__global__ __launch_bounds__(256, 2) void mega_kernel(
    const float* __restrict__ nodef, const float* __restrict__ gf,
    const int* __restrict__ atm, const void* __restrict__ move_mask,
    const void* __restrict__ dvm, const void* __restrict__ mvm,
    const float* __restrict__ cm_W1, const float* __restrict__ cm_W2, const float* __restrict__ cm_b2,
    const float* __restrict__ at_W1, const float* __restrict__ at_b1,
    const float* __restrict__ at_W2, const float* __restrict__ at_b2,
    const float* __restrict__ dk_W1, const float* __restrict__ dk_b1,
    const float* __restrict__ dk_W2, const float* __restrict__ dk_b2,
    const float* __restrict__ dk_W3, const float* __restrict__ dk_b3,
    const float* __restrict__ mn_W1, const float* __restrict__ mn_b1,
    const float* __restrict__ mn_W2, const float* __restrict__ mn_b2,
    float* __restrict__ out_at, float* __restrict__ out_cube,
    float* __restrict__ out_dock, float* __restrict__ out_man)
{
    extern __shared__ __align__(16) char smem_raw[];
    const int t = threadIdx.x;
    const int mode = mask_mode(atm);

    if (blockIdx.x >= 256) {
        // ===================== CUBE (mma.sync bf16) =====================
        uint32_t* Xs  = (uint32_t*)smem_raw;                 // [128][68] bf16x2 (stride 68 u32)
        uint32_t* Ws1 = (uint32_t*)(smem_raw + 34816);       // [128n][68]
        uint32_t* Ws2 = (uint32_t*)(smem_raw + 69632);       // [24n][68]
        float* gcs  = (float*)(smem_raw + 76160);
        float* b2s  = (float*)(smem_raw + 76672);
        int*   nodes = (int*)(smem_raw + 76768);

        const int row0 = (blockIdx.x - 256) * 128;           // 128 rows/block
        const int b = row0 >> 9;
        const int w = t >> 5, lane = t & 31;

        if (t < 128) {
            gcs[t] = d_cm_gc[b * 128 + t];
            if (t < 24) b2s[t] = __ldg(cm_b2 + t);
            // W1^T: thread t owns n=t; coalesced 128B per warp per k
            const float* wp = cm_W1 + t;
            #pragma unroll 8
            for (int kk = 0; kk < 64; kk++) {
                float w0 = __ldg(wp + (2 * kk) * 128);
                float w1 = __ldg(wp + (2 * kk + 1) * 128);
                Ws1[t * 68 + kk] = bf2(w0, w1);
            }
            // W2^T: 24n x 64 kpairs
            for (int idx = t; idx < 24 * 64; idx += 128) {
                int n = idx % 24, kk = idx / 24;
                float w0 = __ldg(cm_W2 + (2 * kk) * 24 + n);
                float w1 = __ldg(cm_W2 + (2 * kk + 1) * 24 + n);
                Ws2[n * 68 + kk] = bf2(w0, w1);
            }
        } else {
            // X: thread owns row r = t-128
            const int r = t - 128;
            const int nd = d_cube_node[row0 + r];
            nodes[r] = nd;
            if (nd >= 0) {
                const float4* xp = (const float4*)(nodef + (size_t)nd * 128);
                #pragma unroll
                for (int i = 0; i < 32; i++) {
                    float4 v = __ldg(xp + i);
                    Xs[r * 68 + 2 * i]     = bf2(v.x, v.y);
                    Xs[r * 68 + 2 * i + 1] = bf2(v.z, v.w);
                }
            } else {
                #pragma unroll
                for (int i = 0; i < 64; i++) Xs[r * 68 + i] = 0u;
            }
        }
        __syncthreads();

        // GEMM1: warp w owns rows 16w..16w+15. 8 k-steps x 16 n-tiles.
        const int gid4 = lane >> 2, tig = lane & 3;
        const int ar0 = 16 * w + gid4;
        const uint32_t* Xr0 = Xs + ar0 * 68 + tig;
        const uint32_t* Xr1 = Xs + (ar0 + 8) * 68 + tig;

        float acc[16][4];
        #pragma unroll
        for (int i = 0; i < 16; i++)
            #pragma unroll
            for (int j = 0; j < 4; j++) acc[i][j] = 0.f;

        #pragma unroll
        for (int ks = 0; ks < 8; ks++) {
            uint32_t a0 = Xr0[8 * ks],     a1 = Xr1[8 * ks];
            uint32_t a2 = Xr0[8 * ks + 4], a3 = Xr1[8 * ks + 4];
            #pragma unroll
            for (int nt = 0; nt < 16; nt++) {
                const uint32_t* bp = Ws1 + (8 * nt + gid4) * 68 + 8 * ks + tig;
                mma16816(acc[nt], a0, a1, a2, a3, bp[0], bp[4]);
            }
        }

        // epilogue1: +gc, relu, bf16x2 -> own rows of Xs (now H)
        #pragma unroll
        for (int nt = 0; nt < 16; nt++) {
            int c0 = 8 * nt + 2 * tig;
            float g0 = gcs[c0], g1 = gcs[c0 + 1];
            Xs[ar0 * 68 + 4 * nt + tig] =
                bf2(fmaxf(acc[nt][0] + g0, 0.f), fmaxf(acc[nt][1] + g1, 0.f));
            Xs[(ar0 + 8) * 68 + 4 * nt + tig] =
                bf2(fmaxf(acc[nt][2] + g0, 0.f), fmaxf(acc[nt][3] + g1, 0.f));
        }
        __syncwarp();

        // GEMM2: H @ W2^T (N=24): 8 k-steps x 3 n-tiles
        float acc2[3][4];
        #pragma unroll
        for (int i = 0; i < 3; i++)
            #pragma unroll
            for (int j = 0; j < 4; j++) acc2[i][j] = 0.f;

        #pragma unroll
        for (int ks = 0; ks < 8; ks++) {
            uint32_t a0 = Xr0[8 * ks],     a1 = Xr1[8 * ks];
            uint32_t a2 = Xr0[8 * ks + 4], a3 = Xr1[8 * ks + 4];
            #pragma unroll
            for (int nt = 0; nt < 3; nt++) {
                const uint32_t* bp = Ws2 + (8 * nt + gid4) * 68 + 8 * ks + tig;
                mma16816(acc2[nt], a0, a1, a2, a3, bp[0], bp[4]);
            }
        }

        const bool v0 = nodes[ar0] >= 0;
        const bool v1 = nodes[ar0 + 8] >= 0;
        #pragma unroll
        for (int nt = 0; nt < 3; nt++) {
            int c0 = 8 * nt + 2 * tig;
            float bb0 = b2s[c0], bb1 = b2s[c0 + 1];
            long o0 = (long)(row0 + ar0) * 24 + c0;
            long o1 = (long)(row0 + ar0 + 8) * 24 + c0;
            out_cube[o0]     = (v0 && read_mask(move_mask, o0, mode))     ? acc2[nt][0] + bb0 : NEG;
            out_cube[o0 + 1] = (v0 && read_mask(move_mask, o0 + 1, mode)) ? acc2[nt][1] + bb1 : NEG;
            out_cube[o1]     = (v1 && read_mask(move_mask, o1, mode))     ? acc2[nt][2] + bb0 : NEG;
            out_cube[o1 + 1] = (v1 && read_mask(move_mask, o1 + 1, mode)) ? acc2[nt][3] + bb1 : NEG;
        }
        return;
    }

    // ===================== HEADS =====================
    const int b = blockIdx.x & 127;
    if (blockIdx.x < 128) {
        // ---------- DOCKING ----------
        float* gf8 = (float*)smem_raw;                    // [8][128]
        float* gl  = (float*)(smem_raw + 4096);
        float* uu  = (float*)(smem_raw + 4608);
        float* vv  = (float*)(smem_raw + 8704);
        float* ww  = (float*)(smem_raw + 12800);
        float* W3s = (float*)(smem_raw + 13312);
        int*   gid = (int*)  (smem_raw + 13568);
        float* W2s = (float*)(smem_raw + 13600);          // [128][64]

        if (t < G_) gid[t] = d_group_node[b * G_ + t];
        if (t >= 128) gl[t - 128] = gf[b * 128 + (t - 128)];
        __syncthreads();
        #pragma unroll
        for (int i = 0; i < 4; i++) {
            int idx = t + i * 256;
            int g = idx >> 7, c = idx & 127;
            int n = gid[g];
            gf8[g * 128 + c] = (n >= 0) ? __ldg(nodef + (size_t)n * 128 + c) : 0.f;
        }
        #pragma unroll
        for (int i = 0; i < 32; i++) W2s[t + i * 256] = __ldg(dk_W2 + t + i * 256);
        if (t < 64) W3s[t] = __ldg(dk_W3 + t);
        __syncthreads();

        if (t < 128) {
            float ua[G_], va[G_];
            #pragma unroll
            for (int g = 0; g < G_; g++) { ua[g] = 0.f; va[g] = 0.f; }
            float wv = __ldg(dk_b1 + t);
            #pragma unroll 4
            for (int k = 0; k < 128; k++) {
                float wa = __ldg(dk_W1 + k * 128 + t);
                float wb = __ldg(dk_W1 + (128 + k) * 128 + t);
                float wc = __ldg(dk_W1 + (256 + k) * 128 + t);
                #pragma unroll
                for (int g = 0; g < G_; g++) {
                    float x = gf8[g * 128 + k];
                    ua[g] = fmaf(x, wa, ua[g]);
                    va[g] = fmaf(x, wb, va[g]);
                }
                wv = fmaf(gl[k], wc, wv);
            }
            #pragma unroll
            for (int g = 0; g < G_; g++) { uu[g * 128 + t] = ua[g]; vv[g * 128 + t] = va[g]; }
            ww[t] = wv;
        }
        __syncthreads();

        // 8 warps x up-to-4 pairs: {w, w+8}, then {w+16, w+24}
        const int wp = t >> 5, lane = t & 31;
        const float b2a = __ldg(dk_b2 + lane);
        const float b2b = __ldg(dk_b2 + lane + 32);
        const float b3v = __ldg(dk_b3);
        const float w3a = W3s[lane], w3b = W3s[lane + 32];

        #pragma unroll
        for (int jj = 0; jj < 2; jj++) {
            const int p0 = wp + 16 * jj;
            const int p1r = p0 + 8;
            const bool has1 = p1r < P_;
            const int p1 = has1 ? p1r : p0;
            const int i0 = c_IU[p0], j0 = c_JU[p0];
            const int i1 = c_IU[p1], j1 = c_JU[p1];
            float s0a = 0.f, s0b = 0.f, s1a = 0.f, s1b = 0.f;
            #pragma unroll 4
            for (int k = 0; k < 128; k++) {
                float wk = ww[k];
                float h0 = fmaxf(uu[i0 * 128 + k] + vv[j0 * 128 + k] + wk, 0.f);
                float h1 = fmaxf(uu[i1 * 128 + k] + vv[j1 * 128 + k] + wk, 0.f);
                float w2a = W2s[k * 64 + lane];
                float w2b = W2s[k * 64 + lane + 32];
                s0a = fmaf(h0, w2a, s0a);
                s0b = fmaf(h0, w2b, s0b);
                s1a = fmaf(h1, w2a, s1a);
                s1b = fmaf(h1, w2b, s1b);
            }
            float c0 = fmaxf(s0a + b2a, 0.f) * w3a + fmaxf(s0b + b2b, 0.f) * w3b;
            float c1 = fmaxf(s1a + b2a, 0.f) * w3a + fmaxf(s1b + b2b, 0.f) * w3b;
            #pragma unroll
            for (int off = 16; off; off >>= 1) {
                c0 += __shfl_down_sync(0xffffffffu, c0, off);
                c1 += __shfl_down_sync(0xffffffffu, c1, off);
            }
            if (lane == 0) {
                bool ok0 = read_mask(dvm, b * P_ + p0, mode) && gid[i0] >= 0 && gid[j0] >= 0;
                out_dock[b * P_ + p0] = ok0 ? (c0 + b3v) : NEG;
                if (has1) {
                    bool ok1 = read_mask(dvm, b * P_ + p1, mode) && gid[i1] >= 0 && gid[j1] >= 0;
                    out_dock[b * P_ + p1] = ok1 ? (c1 + b3v) : NEG;
                }
            }
        }
    } else {
        // ---------- MANEUVER + ACTION TYPE ----------
        float* gf8  = (float*)smem_raw;
        float* gl   = (float*)(smem_raw + 4096);
        float* manH = (float*)(smem_raw + 4608);
        float* ath  = (float*)(smem_raw + 8704);
        float* W2m  = (float*)(smem_raw + 8960);
        int*   gid  = (int*)  (smem_raw + 12544);

        if (t < G_) gid[t] = d_group_node[b * G_ + t];
        if (t >= 128) gl[t - 128] = gf[b * 128 + (t - 128)];
        __syncthreads();
        #pragma unroll
        for (int i = 0; i < 4; i++) {
            int idx = t + i * 256;
            int g = idx >> 7, c = idx & 127;
            int n = gid[g];
            gf8[g * 128 + c] = (n >= 0) ? __ldg(nodef + (size_t)n * 128 + c) : 0.f;
        }
        for (int idx = t; idx < 128 * ND_; idx += 256) W2m[idx] = __ldg(mn_W2 + idx);
        __syncthreads();

        if (t < 128) {
            float ma[G_];
            #pragma unroll
            for (int g = 0; g < G_; g++) ma[g] = 0.f;
            float gcm = __ldg(mn_b1 + t);
            float av = (t < 64) ? __ldg(at_b1 + t) : 0.f;
            #pragma unroll 4
            for (int k = 0; k < 128; k++) {
                float wa = __ldg(mn_W1 + k * 128 + t);
                float wb = __ldg(mn_W1 + (128 + k) * 128 + t);
                float gk = gl[k];
                #pragma unroll
                for (int g = 0; g < G_; g++) ma[g] = fmaf(gf8[g * 128 + k], wa, ma[g]);
                gcm = fmaf(gk, wb, gcm);
                if (t < 64) av = fmaf(gk, __ldg(at_W1 + k * 64 + t), av);
            }
            #pragma unroll
            for (int g = 0; g < G_; g++) manH[g * 128 + t] = fmaxf(ma[g] + gcm, 0.f);
            if (t < 64) ath[t] = fmaxf(av, 0.f);
        }
        __syncthreads();

        if (t < G_ * ND_) {
            int g = t / ND_, d = t - g * ND_;
            float s = __ldg(mn_b2 + d);
            #pragma unroll 8
            for (int k = 0; k < 128; k++) s = fmaf(manH[g * 128 + k], W2m[k * ND_ + d], s);
            bool ok = (gid[g] >= 0) && read_mask(mvm, b * G_ * ND_ + t, mode);
            out_man[b * G_ * ND_ + t] = ok ? s : NEG;
        } else if (t >= 64 && t < 64 + AT_) {
            int a = t - 64;
            float s = __ldg(at_b2 + a);
            #pragma unroll 8
            for (int k = 0; k < 64; k++) s = fmaf(ath[k], __ldg(at_W2 + k * AT_ + a), s);
            out_at[b * AT_ + a] = read_mask(atm, b * AT_ + a, mode) ? s : NEG;
        }
    }
}

// ---------------------------------------------------------------------------
extern "C" void kernel_launch(void* const* d_in, const int* in_sizes, int n_in,
                              void* d_out, int out_size) {
    const float* nodef      = (const float*)d_in[0];
    const float* gf         = (const float*)d_in[1];
    const int*   atm        = (const int*)d_in[2];
    const void*  cube_mask  = d_in[3];
    const void*  group_mask = d_in[4];
    /* d_in[5] = batch (unused; segments contiguous) */
    const void*  move_mask  = d_in[6];
    const void*  dvm        = d_in[7];
    const void*  mvm        = d_in[8];
    const float* at_W1 = (const float*)d_in[9];
    const float* at_b1 = (const float*)d_in[10];
    const float* at_W2 = (const float*)d_in[11];
    const float* at_b2 = (const float*)d_in[12];
    const float* cm_W1 = (const float*)d_in[13];
    const float* cm_b1 = (const float*)d_in[14];
    const float* cm_W2 = (const float*)d_in[15];
    const float* cm_b2 = (const float*)d_in[16];
    const float* dk_W1 = (const float*)d_in[17];
    const float* dk_b1 = (const float*)d_in[18];
    const float* dk_W2 = (const float*)d_in[19];
    const float* dk_b2 = (const float*)d_in[20];
    const float* dk_W3 = (const float*)d_in[21];
    const float* dk_b3 = (const float*)d_in[22];
    const float* mn_W1 = (const float*)d_in[23];
    const float* mn_b1 = (const float*)d_in[24];
    const float* mn_W2 = (const float*)d_in[25];
    const float* mn_b2 = (const float*)d_in[26];

    float* out      = (float*)d_out;
    float* out_at   = out;
    float* out_cube = out + (size_t)B_ * AT_;
    float* out_dock = out_cube + (size_t)B_ * MAXC * M_;
    float* out_man  = out_dock + (size_t)B_ * P_;

    cudaFuncSetAttribute(mega_kernel, cudaFuncAttributeMaxDynamicSharedMemorySize, SMEM_DYN);

    setup_kernel<<<B_, 256>>>(gf, cm_W1, cm_b1, cube_mask, group_mask, atm);
    mega_kernel<<<256 + (B_ * MAXC) / 128, 256, SMEM_DYN>>>(
        nodef, gf, atm, move_mask, dvm, mvm,
        cm_W1, cm_W2, cm_b2,
        at_W1, at_b1, at_W2, at_b2,
        dk_W1, dk_b1, dk_W2, dk_b2, dk_W3, dk_b3,
        mn_W1, mn_b1, mn_W2, mn_b2,
        out_at, out_cube, out_dock, out_man);
}

// round 9
// speedup vs baseline: 4.6292x; 1.1691x over previous
#include <cuda_runtime.h>
#include <cuda_bf16.h>
#include <stdint.h>

#define NEG (-1e9f)
constexpr int B_   = 128;
constexpr int NPG  = 1024;
constexpr int M_   = 24;
constexpr int MAXC = 512;
constexpr int G_   = 8;
constexpr int ND_  = 7;
constexpr int AT_  = 5;
constexpr int P_   = 28;

__device__ int   d_cube_node[B_ * MAXC];
__device__ int   d_group_node[B_ * G_];
__device__ float d_cm_gc[B_ * 128];

__constant__ int c_IU[P_] = {0,0,0,0,0,0,0,1,1,1,1,1,1,2,2,2,2,2,3,3,3,3,4,4,4,5,5,6};
__constant__ int c_JU[P_] = {1,2,3,4,5,6,7,2,3,4,5,6,7,3,4,5,6,7,4,5,6,7,5,6,7,6,7,7};

__device__ __forceinline__ int mask_mode(const int* __restrict__ atm) {
    int v = __ldg(atm);
    if (v == 1) return 1;
    if (v == 0x3F800000) return 2;
    return 0;
}
__device__ __forceinline__ bool read_mask(const void* p, long i, int mode) {
    if (mode == 1) return ((const int*)p)[i] != 0;
    if (mode == 2) return ((const float*)p)[i] != 0.f;
    return ((const uint8_t*)p)[i] != 0;
}

// bf16 mma.sync (sm_80+ baseline PTX -> HMMA on sm_103)
__device__ __forceinline__ void mma16816(float* c, uint32_t a0, uint32_t a1,
                                         uint32_t a2, uint32_t a3,
                                         uint32_t b0, uint32_t b1) {
    asm volatile(
        "mma.sync.aligned.m16n8k16.row.col.f32.bf16.bf16.f32 "
        "{%0,%1,%2,%3}, {%4,%5,%6,%7}, {%8,%9}, {%0,%1,%2,%3};"
        : "+f"(c[0]), "+f"(c[1]), "+f"(c[2]), "+f"(c[3])
        : "r"(a0), "r"(a1), "r"(a2), "r"(a3), "r"(b0), "r"(b1));
}
__device__ __forceinline__ uint32_t bf2(float x, float y) {
    __nv_bfloat162 p = __float22bfloat162_rn(make_float2(x, y));
    return *(uint32_t*)&p;
}

// ---------------------------------------------------------------------------
// setup: warps 0-3 gcontrib (k-split, float4), warps 4-7 parallel index scan
// ---------------------------------------------------------------------------
__global__ __launch_bounds__(256) void setup_kernel(
    const float* __restrict__ gf,
    const float* __restrict__ cmW1, const float* __restrict__ cmb1,
    const void* __restrict__ cube_mask, const void* __restrict__ group_mask,
    const int* __restrict__ atm)
{
    const int b = blockIdx.x, t = threadIdx.x;
    const int w = t >> 5, lane = t & 31;
    const int mode = mask_mode(atm);
    __shared__ float g[128];
    __shared__ float sred[4][128];
    __shared__ int wtc[4], wtg[4], stc, stg;

    if (t < 128) g[t] = gf[b * 128 + t];
    __syncthreads();

    unsigned cm8 = 0, gm8 = 0;
    int cex = 0, gex = 0;

    if (w < 4) {
        const float4* W4 = (const float4*)cmW1;
        float4 a = make_float4(0.f, 0.f, 0.f, 0.f);
        #pragma unroll
        for (int kk = 0; kk < 32; kk++) {
            int k = 32 * w + kk;
            float4 wv = __ldg(&W4[(128 + k) * 32 + lane]);
            float gk = g[k];
            a.x = fmaf(gk, wv.x, a.x);
            a.y = fmaf(gk, wv.y, a.y);
            a.z = fmaf(gk, wv.z, a.z);
            a.w = fmaf(gk, wv.w, a.w);
        }
        *(float4*)&sred[w][4 * lane] = a;
    } else if (mode == 1) {
        const int w4 = w - 4;
        const int4* cm4 = (const int4*)cube_mask + b * 256 + w4 * 64 + lane * 2;
        const int4* gm4 = (const int4*)group_mask + b * 256 + w4 * 64 + lane * 2;
        int4 c0 = __ldg(cm4), c1 = __ldg(cm4 + 1);
        int4 g0 = __ldg(gm4), g1 = __ldg(gm4 + 1);
        cm8 = (c0.x != 0) | ((c0.y != 0) << 1) | ((c0.z != 0) << 2) | ((c0.w != 0) << 3)
            | ((c1.x != 0) << 4) | ((c1.y != 0) << 5) | ((c1.z != 0) << 6) | ((c1.w != 0) << 7);
        gm8 = (g0.x != 0) | ((g0.y != 0) << 1) | ((g0.z != 0) << 2) | ((g0.w != 0) << 3)
            | ((g1.x != 0) << 4) | ((g1.y != 0) << 5) | ((g1.z != 0) << 6) | ((g1.w != 0) << 7);
        int cs = __popc(cm8), gs = __popc(gm8);
        int csi = cs, gsi = gs;
        #pragma unroll
        for (int off = 1; off < 32; off <<= 1) {
            int v1 = __shfl_up_sync(0xffffffffu, csi, off);
            int v2 = __shfl_up_sync(0xffffffffu, gsi, off);
            if (lane >= off) { csi += v1; gsi += v2; }
        }
        cex = csi - cs; gex = gsi - gs;
        if (lane == 31) { wtc[w4] = csi; wtg[w4] = gsi; }
    } else if (w == 4) {
        int cc = 0, gc = 0;
        for (int c = 0; c < NPG; c += 32) {
            long node = (long)b * NPG + c + lane;
            bool cm = read_mask(cube_mask, node, mode);
            bool gm = read_mask(group_mask, node, mode);
            unsigned cb = __ballot_sync(0xffffffffu, cm);
            unsigned gb = __ballot_sync(0xffffffffu, gm);
            unsigned lt = (1u << lane) - 1u;
            if (cm) { int p = cc + __popc(cb & lt); if (p < MAXC) d_cube_node[b * MAXC + p] = (int)node; }
            if (gm) { int p = gc + __popc(gb & lt); if (p < G_)   d_group_node[b * G_ + p] = (int)node; }
            cc += __popc(cb);
            gc += __popc(gb);
        }
        if (lane == 0) { stc = cc; stg = gc; }
    }
    __syncthreads();

    if (t < 128)
        d_cm_gc[b * 128 + t] = __ldg(cmb1 + t) +
            ((sred[0][t] + sred[1][t]) + (sred[2][t] + sred[3][t]));

    int tc, tg;
    if (mode == 1) {
        tc = wtc[0] + wtc[1] + wtc[2] + wtc[3];
        tg = wtg[0] + wtg[1] + wtg[2] + wtg[3];
        if (w >= 4) {
            const int w4 = w - 4;
            int cbase = 0, gbase = 0;
            #pragma unroll
            for (int i = 0; i < 4; i++) if (i < w4) { cbase += wtc[i]; gbase += wtg[i]; }
            const int nb = b * NPG + w4 * 256 + lane * 8;
            #pragma unroll
            for (int j = 0; j < 8; j++) {
                if ((cm8 >> j) & 1) {
                    int p = cbase + cex + __popc(cm8 & ((1u << j) - 1u));
                    if (p < MAXC) d_cube_node[b * MAXC + p] = nb + j;
                }
                if ((gm8 >> j) & 1) {
                    int p = gbase + gex + __popc(gm8 & ((1u << j) - 1u));
                    if (p < G_) d_group_node[b * G_ + p] = nb + j;
                }
            }
        }
    } else {
        tc = stc; tg = stg;
    }
    for (int p = tc + t; p < MAXC; p += 256) d_cube_node[b * MAXC + p] = -1;
    for (int p = tg + t; p < G_; p += 256)   d_group_node[b * G_ + p] = -1;
}

// ---------------------------------------------------------------------------
// mega kernel, 256 threads/block:
//   blocks 0-127 docking, 128-255 maneuver+AT, 256-767 cube (mma.sync bf16)
// cube dyn smem map (bytes):
//   Xs/Ds 0..34816 | Ws1 34816..69632 | Ws2 69632..76160
//   gcs 76160..76672 | b2s 76672..76768 | nodes 76768..77280
// ---------------------------------------------------------------------------
constexpr int SMEM_DYN = 77280;

__global__ __launch_bounds__(256, 2) void mega_kernel(
    const float* __restrict__ nodef, const float* __restrict__ gf,
    const int* __restrict__ atm, const void* __restrict__ move_mask,
    const void* __restrict__ dvm, const void* __restrict__ mvm,
    const float* __restrict__ cm_W1, const float* __restrict__ cm_W2, const float* __restrict__ cm_b2,
    const float* __restrict__ at_W1, const float* __restrict__ at_b1,
    const float* __restrict__ at_W2, const float* __restrict__ at_b2,
    const float* __restrict__ dk_W1, const float* __restrict__ dk_b1,
    const float* __restrict__ dk_W2, const float* __restrict__ dk_b2,
    const float* __restrict__ dk_W3, const float* __restrict__ dk_b3,
    const float* __restrict__ mn_W1, const float* __restrict__ mn_b1,
    const float* __restrict__ mn_W2, const float* __restrict__ mn_b2,
    float* __restrict__ out_at, float* __restrict__ out_cube,
    float* __restrict__ out_dock, float* __restrict__ out_man)
{
    extern __shared__ __align__(16) char smem_raw[];
    const int t = threadIdx.x;
    const int mode = mask_mode(atm);

    if (blockIdx.x >= 256) {
        // ===================== CUBE (mma.sync bf16) =====================
        uint32_t* Xs  = (uint32_t*)smem_raw;                 // [128][68] bf16x2
        float*    Ds  = (float*)smem_raw;                    // reuse after GEMM2
        uint32_t* Ws1 = (uint32_t*)(smem_raw + 34816);       // [128n][68]
        uint32_t* Ws2 = (uint32_t*)(smem_raw + 69632);       // [24n][68]
        float* gcs  = (float*)(smem_raw + 76160);
        float* b2s  = (float*)(smem_raw + 76672);
        int*   nodes = (int*)(smem_raw + 76768);

        const int row0 = (blockIdx.x - 256) * 128;           // 128 rows/block
        const int b = row0 >> 9;
        const int w = t >> 5, lane = t & 31;

        if (t < 128) {
            nodes[t] = d_cube_node[row0 + t];
            gcs[t] = d_cm_gc[b * 128 + t];
            if (t < 24) b2s[t] = __ldg(cm_b2 + t);
        }
        __syncthreads();

        // W1^T staging split over 256 threads: n = t&127, k-half by t>>7
        {
            const int n = t & 127, kh = (t >> 7) * 32;
            const float* wp = cm_W1 + n;
            #pragma unroll 8
            for (int kk = 0; kk < 32; kk++) {
                int k2 = kh + kk;
                float w0 = __ldg(wp + (2 * k2) * 128);
                float w1 = __ldg(wp + (2 * k2 + 1) * 128);
                Ws1[n * 68 + k2] = bf2(w0, w1);
            }
        }
        // W2^T: 24n x 64 kpairs
        for (int idx = t; idx < 24 * 64; idx += 256) {
            int n = idx % 24, kk = idx / 24;
            float w0 = __ldg(cm_W2 + (2 * kk) * 24 + n);
            float w1 = __ldg(cm_W2 + (2 * kk + 1) * 24 + n);
            Ws2[n * 68 + kk] = bf2(w0, w1);
        }
        // X: warp-per-row cooperative, lane l <-> float4 l of the row (coalesced)
        #pragma unroll
        for (int i = 0; i < 16; i++) {
            int r = 16 * w + i;
            int nd = nodes[r];
            uint64_t v = 0ull;
            if (nd >= 0) {
                float4 x = __ldg((const float4*)(nodef + (size_t)nd * 128) + lane);
                v = ((uint64_t)bf2(x.z, x.w) << 32) | (uint64_t)bf2(x.x, x.y);
            }
            *(uint64_t*)&Xs[r * 68 + 2 * lane] = v;
        }
        __syncthreads();

        // GEMM1: warp w owns rows 16w..16w+15. 8 k-steps x 16 n-tiles.
        const int gid4 = lane >> 2, tig = lane & 3;
        const int ar0 = 16 * w + gid4;
        const uint32_t* Xr0 = Xs + ar0 * 68 + tig;
        const uint32_t* Xr1 = Xs + (ar0 + 8) * 68 + tig;

        float acc[16][4];
        #pragma unroll
        for (int i = 0; i < 16; i++)
            #pragma unroll
            for (int j = 0; j < 4; j++) acc[i][j] = 0.f;

        #pragma unroll
        for (int ks = 0; ks < 8; ks++) {
            uint32_t a0 = Xr0[8 * ks],     a1 = Xr1[8 * ks];
            uint32_t a2 = Xr0[8 * ks + 4], a3 = Xr1[8 * ks + 4];
            #pragma unroll
            for (int nt = 0; nt < 16; nt++) {
                const uint32_t* bp = Ws1 + (8 * nt + gid4) * 68 + 8 * ks + tig;
                mma16816(acc[nt], a0, a1, a2, a3, bp[0], bp[4]);
            }
        }

        // epilogue1: +gc, relu, bf16x2 -> own rows of Xs (now H)
        #pragma unroll
        for (int nt = 0; nt < 16; nt++) {
            int c0 = 8 * nt + 2 * tig;
            float g0 = gcs[c0], g1 = gcs[c0 + 1];
            Xs[ar0 * 68 + 4 * nt + tig] =
                bf2(fmaxf(acc[nt][0] + g0, 0.f), fmaxf(acc[nt][1] + g1, 0.f));
            Xs[(ar0 + 8) * 68 + 4 * nt + tig] =
                bf2(fmaxf(acc[nt][2] + g0, 0.f), fmaxf(acc[nt][3] + g1, 0.f));
        }
        __syncwarp();

        // GEMM2: H @ W2^T (N=24): 8 k-steps x 3 n-tiles
        float acc2[3][4];
        #pragma unroll
        for (int i = 0; i < 3; i++)
            #pragma unroll
            for (int j = 0; j < 4; j++) acc2[i][j] = 0.f;

        #pragma unroll
        for (int ks = 0; ks < 8; ks++) {
            uint32_t a0 = Xr0[8 * ks],     a1 = Xr1[8 * ks];
            uint32_t a2 = Xr0[8 * ks + 4], a3 = Xr1[8 * ks + 4];
            #pragma unroll
            for (int nt = 0; nt < 3; nt++) {
                const uint32_t* bp = Ws2 + (8 * nt + gid4) * 68 + 8 * ks + tig;
                mma16816(acc2[nt], a0, a1, a2, a3, bp[0], bp[4]);
            }
        }
        __syncthreads();        // all Xs reads complete before Ds overwrite

        // stage D2 + bias into smem (Ds[r][c], r-major, 24 floats/row)
        #pragma unroll
        for (int nt = 0; nt < 3; nt++) {
            int c0 = 8 * nt + 2 * tig;
            float bb0 = b2s[c0], bb1 = b2s[c0 + 1];
            Ds[ar0 * 24 + c0]           = acc2[nt][0] + bb0;
            Ds[ar0 * 24 + c0 + 1]       = acc2[nt][1] + bb1;
            Ds[(ar0 + 8) * 24 + c0]     = acc2[nt][2] + bb0;
            Ds[(ar0 + 8) * 24 + c0 + 1] = acc2[nt][3] + bb1;
        }
        __syncthreads();

        // linear masked write: 3072 floats = 768 float4, coalesced loads/stores
        const long ebase = (long)row0 * 24;
        #pragma unroll
        for (int i = 0; i < 3; i++) {
            int idx4 = t + i * 256;
            float4 v = ((const float4*)Ds)[idx4];
            float r4[4] = {v.x, v.y, v.z, v.w};
            float o4[4];
            if (mode == 1) {
                int4 mk = __ldg((const int4*)move_mask + row0 * 6 + idx4);
                int m4[4] = {mk.x, mk.y, mk.z, mk.w};
                #pragma unroll
                for (int j = 0; j < 4; j++) {
                    int e = idx4 * 4 + j;
                    bool ok = (nodes[e / 24] >= 0) && (m4[j] != 0);
                    o4[j] = ok ? r4[j] : NEG;
                }
            } else {
                #pragma unroll
                for (int j = 0; j < 4; j++) {
                    int e = idx4 * 4 + j;
                    bool ok = (nodes[e / 24] >= 0) && read_mask(move_mask, ebase + e, mode);
                    o4[j] = ok ? r4[j] : NEG;
                }
            }
            *(float4*)(out_cube + ebase + idx4 * 4) = make_float4(o4[0], o4[1], o4[2], o4[3]);
        }
        return;
    }

    // ===================== HEADS =====================
    const int b = blockIdx.x & 127;
    if (blockIdx.x < 128) {
        // ---------- DOCKING ----------
        float* gf8 = (float*)smem_raw;                    // [8][128]
        float* gl  = (float*)(smem_raw + 4096);
        float* uu  = (float*)(smem_raw + 4608);
        float* vv  = (float*)(smem_raw + 8704);
        float* ww  = (float*)(smem_raw + 12800);
        float* W3s = (float*)(smem_raw + 13312);
        int*   gid = (int*)  (smem_raw + 13568);
        float* W2s = (float*)(smem_raw + 13600);          // [128][64]

        if (t < G_) gid[t] = d_group_node[b * G_ + t];
        if (t >= 128) gl[t - 128] = gf[b * 128 + (t - 128)];
        __syncthreads();
        #pragma unroll
        for (int i = 0; i < 4; i++) {
            int idx = t + i * 256;
            int g = idx >> 7, c = idx & 127;
            int n = gid[g];
            gf8[g * 128 + c] = (n >= 0) ? __ldg(nodef + (size_t)n * 128 + c) : 0.f;
        }
        #pragma unroll
        for (int i = 0; i < 32; i++) W2s[t + i * 256] = __ldg(dk_W2 + t + i * 256);
        if (t < 64) W3s[t] = __ldg(dk_W3 + t);
        __syncthreads();

        if (t < 128) {
            float ua[G_], va[G_];
            #pragma unroll
            for (int g = 0; g < G_; g++) { ua[g] = 0.f; va[g] = 0.f; }
            float wv = __ldg(dk_b1 + t);
            #pragma unroll 4
            for (int k = 0; k < 128; k++) {
                float wa = __ldg(dk_W1 + k * 128 + t);
                float wb = __ldg(dk_W1 + (128 + k) * 128 + t);
                float wc = __ldg(dk_W1 + (256 + k) * 128 + t);
                #pragma unroll
                for (int g = 0; g < G_; g++) {
                    float x = gf8[g * 128 + k];
                    ua[g] = fmaf(x, wa, ua[g]);
                    va[g] = fmaf(x, wb, va[g]);
                }
                wv = fmaf(gl[k], wc, wv);
            }
            #pragma unroll
            for (int g = 0; g < G_; g++) { uu[g * 128 + t] = ua[g]; vv[g * 128 + t] = va[g]; }
            ww[t] = wv;
        }
        __syncthreads();

        const int wp = t >> 5, lane = t & 31;
        const float b2a = __ldg(dk_b2 + lane);
        const float b2b = __ldg(dk_b2 + lane + 32);
        const float b3v = __ldg(dk_b3);
        const float w3a = W3s[lane], w3b = W3s[lane + 32];

        #pragma unroll
        for (int jj = 0; jj < 2; jj++) {
            const int p0 = wp + 16 * jj;
            const int p1r = p0 + 8;
            const bool has1 = p1r < P_;
            const int p1 = has1 ? p1r : p0;
            const int i0 = c_IU[p0], j0 = c_JU[p0];
            const int i1 = c_IU[p1], j1 = c_JU[p1];
            float s0a = 0.f, s0b = 0.f, s1a = 0.f, s1b = 0.f;
            #pragma unroll 4
            for (int k = 0; k < 128; k++) {
                float wk = ww[k];
                float h0 = fmaxf(uu[i0 * 128 + k] + vv[j0 * 128 + k] + wk, 0.f);
                float h1 = fmaxf(uu[i1 * 128 + k] + vv[j1 * 128 + k] + wk, 0.f);
                float w2a = W2s[k * 64 + lane];
                float w2b = W2s[k * 64 + lane + 32];
                s0a = fmaf(h0, w2a, s0a);
                s0b = fmaf(h0, w2b, s0b);
                s1a = fmaf(h1, w2a, s1a);
                s1b = fmaf(h1, w2b, s1b);
            }
            float c0 = fmaxf(s0a + b2a, 0.f) * w3a + fmaxf(s0b + b2b, 0.f) * w3b;
            float c1 = fmaxf(s1a + b2a, 0.f) * w3a + fmaxf(s1b + b2b, 0.f) * w3b;
            #pragma unroll
            for (int off = 16; off; off >>= 1) {
                c0 += __shfl_down_sync(0xffffffffu, c0, off);
                c1 += __shfl_down_sync(0xffffffffu, c1, off);
            }
            if (lane == 0) {
                bool ok0 = read_mask(dvm, b * P_ + p0, mode) && gid[i0] >= 0 && gid[j0] >= 0;
                out_dock[b * P_ + p0] = ok0 ? (c0 + b3v) : NEG;
                if (has1) {
                    bool ok1 = read_mask(dvm, b * P_ + p1, mode) && gid[i1] >= 0 && gid[j1] >= 0;
                    out_dock[b * P_ + p1] = ok1 ? (c1 + b3v) : NEG;
                }
            }
        }
    } else {
        // ---------- MANEUVER + ACTION TYPE ----------
        float* gf8  = (float*)smem_raw;
        float* gl   = (float*)(smem_raw + 4096);
        float* manH = (float*)(smem_raw + 4608);
        float* ath  = (float*)(smem_raw + 8704);
        float* W2m  = (float*)(smem_raw + 8960);
        int*   gid  = (int*)  (smem_raw + 12544);

        if (t < G_) gid[t] = d_group_node[b * G_ + t];
        if (t >= 128) gl[t - 128] = gf[b * 128 + (t - 128)];
        __syncthreads();
        #pragma unroll
        for (int i = 0; i < 4; i++) {
            int idx = t + i * 256;
            int g = idx >> 7, c = idx & 127;
            int n = gid[g];
            gf8[g * 128 + c] = (n >= 0) ? __ldg(nodef + (size_t)n * 128 + c) : 0.f;
        }
        for (int idx = t; idx < 128 * ND_; idx += 256) W2m[idx] = __ldg(mn_W2 + idx);
        __syncthreads();

        if (t < 128) {
            float ma[G_];
            #pragma unroll
            for (int g = 0; g < G_; g++) ma[g] = 0.f;
            float gcm = __ldg(mn_b1 + t);
            float av = (t < 64) ? __ldg(at_b1 + t) : 0.f;
            #pragma unroll 4
            for (int k = 0; k < 128; k++) {
                float wa = __ldg(mn_W1 + k * 128 + t);
                float wb = __ldg(mn_W1 + (128 + k) * 128 + t);
                float gk = gl[k];
                #pragma unroll
                for (int g = 0; g < G_; g++) ma[g] = fmaf(gf8[g * 128 + k], wa, ma[g]);
                gcm = fmaf(gk, wb, gcm);
                if (t < 64) av = fmaf(gk, __ldg(at_W1 + k * 64 + t), av);
            }
            #pragma unroll
            for (int g = 0; g < G_; g++) manH[g * 128 + t] = fmaxf(ma[g] + gcm, 0.f);
            if (t < 64) ath[t] = fmaxf(av, 0.f);
        }
        __syncthreads();

        if (t < G_ * ND_) {
            int g = t / ND_, d = t - g * ND_;
            float s = __ldg(mn_b2 + d);
            #pragma unroll 8
            for (int k = 0; k < 128; k++) s = fmaf(manH[g * 128 + k], W2m[k * ND_ + d], s);
            bool ok = (gid[g] >= 0) && read_mask(mvm, b * G_ * ND_ + t, mode);
            out_man[b * G_ * ND_ + t] = ok ? s : NEG;
        } else if (t >= 64 && t < 64 + AT_) {
            int a = t - 64;
            float s = __ldg(at_b2 + a);
            #pragma unroll 8
            for (int k = 0; k < 64; k++) s = fmaf(ath[k], __ldg(at_W2 + k * AT_ + a), s);
            out_at[b * AT_ + a] = read_mask(atm, b * AT_ + a, mode) ? s : NEG;
        }
    }
}

// ---------------------------------------------------------------------------
extern "C" void kernel_launch(void* const* d_in, const int* in_sizes, int n_in,
                              void* d_out, int out_size) {
    const float* nodef      = (const float*)d_in[0];
    const float* gf         = (const float*)d_in[1];
    const int*   atm        = (const int*)d_in[2];
    const void*  cube_mask  = d_in[3];
    const void*  group_mask = d_in[4];
    /* d_in[5] = batch (unused; segments contiguous) */
    const void*  move_mask  = d_in[6];
    const void*  dvm        = d_in[7];
    const void*  mvm        = d_in[8];
    const float* at_W1 = (const float*)d_in[9];
    const float* at_b1 = (const float*)d_in[10];
    const float* at_W2 = (const float*)d_in[11];
    const float* at_b2 = (const float*)d_in[12];
    const float* cm_W1 = (const float*)d_in[13];
    const float* cm_b1 = (const float*)d_in[14];
    const float* cm_W2 = (const float*)d_in[15];
    const float* cm_b2 = (const float*)d_in[16];
    const float* dk_W1 = (const float*)d_in[17];
    const float* dk_b1 = (const float*)d_in[18];
    const float* dk_W2 = (const float*)d_in[19];
    const float* dk_b2 = (const float*)d_in[20];
    const float* dk_W3 = (const float*)d_in[21];
    const float* dk_b3 = (const float*)d_in[22];
    const float* mn_W1 = (const float*)d_in[23];
    const float* mn_b1 = (const float*)d_in[24];
    const float* mn_W2 = (const float*)d_in[25];
    const float* mn_b2 = (const float*)d_in[26];

    float* out      = (float*)d_out;
    float* out_at   = out;
    float* out_cube = out + (size_t)B_ * AT_;
    float* out_dock = out_cube + (size_t)B_ * MAXC * M_;
    float* out_man  = out_dock + (size_t)B_ * P_;

    cudaFuncSetAttribute(mega_kernel, cudaFuncAttributeMaxDynamicSharedMemorySize, SMEM_DYN);

    setup_kernel<<<B_, 256>>>(gf, cm_W1, cm_b1, cube_mask, group_mask, atm);
    mega_kernel<<<256 + (B_ * MAXC) / 128, 256, SMEM_DYN>>>(
        nodef, gf, atm, move_mask, dvm, mvm,
        cm_W1, cm_W2, cm_b2,
        at_W1, at_b1, at_W2, at_b2,
        dk_W1, dk_b1, dk_W2, dk_b2, dk_W3, dk_b3,
        mn_W1, mn_b1, mn_W2, mn_b2,
        out_at, out_cube, out_dock, out_man);
}